// round 1
// baseline (speedup 1.0000x reference)
#include <cuda_runtime.h>
#include <math.h>

#define BB 8
#define TT 4096
#define DD 768
#define DI 1536
#define BT (BB*TT)          // 32768 rows
#define CH 128              // re-chunked scan size (equivalent to reference C=64)
#define NCH (TT/CH)         // 32 chunks
#define EPS 1e-5f

// ---------------- scratch (device globals; no allocation allowed) ----------
__device__ float g_xn[BT*DD];                 // rmsnorm output
__device__ float g_val[50331648];             // BT*DI pre-conv projection
__device__ float g_gate[50331648];            // BT*DI gate pre-activation
__device__ float g_u[50331648];               // BT*DI silu(conv)*silu(gate)
__device__ float g_out[BT*DD];                // conv-mix output (= rk, source of wk)
__device__ float g_v[BT*DD];                  // write projection
__device__ float g_reads[BT*DD];              // attention reads
__device__ float g_W[BB*DD*DD];               // recurrent state [b][dv][dk]
__device__ float g_SM[BB*CH*CH];              // per-chunk masked S, [b][c][e]

// ---------------- rmsnorm ---------------------------------------------------
__global__ void rmsnorm_k(const float* __restrict__ x, const float* __restrict__ w) {
    int row = blockIdx.x;
    const float* xr = x + (size_t)row*DD;
    float* o = g_xn + (size_t)row*DD;
    float s = 0.f;
    for (int d = threadIdx.x; d < DD; d += blockDim.x) { float v = xr[d]; s += v*v; }
    __shared__ float red[32];
    for (int off = 16; off; off >>= 1) s += __shfl_down_sync(0xffffffffu, s, off);
    if ((threadIdx.x & 31) == 0) red[threadIdx.x >> 5] = s;
    __syncthreads();
    if (threadIdx.x < 32) {
        float t = (threadIdx.x < (blockDim.x >> 5)) ? red[threadIdx.x] : 0.f;
        for (int off = 16; off; off >>= 1) t += __shfl_down_sync(0xffffffffu, t, off);
        if (threadIdx.x == 0) red[0] = t;
    }
    __syncthreads();
    float scale = rsqrtf(red[0] / (float)DD + EPS);
    for (int d = threadIdx.x; d < DD; d += blockDim.x) o[d] = xr[d] * scale * w[d];
}

// ---------------- generic fp32 GEMM, C[M,N] = A[M,K] @ Bw[N,K]^T ------------
// EPI=0: plain store. EPI=1: C = base1 + base2 + exp(*log_alpha)*acc
template<int EPI>
__global__ void __launch_bounds__(256, 2)
gemm_nt(const float* __restrict__ A, const float* __restrict__ Bw,
        float* __restrict__ C, int M, int N, int K,
        const float* __restrict__ base1, const float* __restrict__ base2,
        const float* __restrict__ log_alpha)
{
    const int BK = 16, PAD = 20;
    __shared__ float As[128*PAD];
    __shared__ float Bs[128*PAD];
    int bm = blockIdx.y * 128, bn = blockIdx.x * 128;
    int tid = threadIdx.x;
    int tx = tid & 15, ty = tid >> 4;
    float acc[8][8];
    #pragma unroll
    for (int i = 0; i < 8; i++)
        #pragma unroll
        for (int j = 0; j < 8; j++) acc[i][j] = 0.f;

    for (int k0 = 0; k0 < K; k0 += BK) {
        #pragma unroll
        for (int s = 0; s < 2; s++) {
            int q = tid + 256*s;
            int r = q >> 2, kc = (q & 3) << 2;
            float4 va = *(const float4*)(A  + (size_t)(bm + r)*K + k0 + kc);
            *(float4*)&As[r*PAD + kc] = va;
            float4 vb = *(const float4*)(Bw + (size_t)(bn + r)*K + k0 + kc);
            *(float4*)&Bs[r*PAD + kc] = vb;
        }
        __syncthreads();
        #pragma unroll
        for (int kk = 0; kk < BK; kk++) {
            float ra[8], rb[8];
            #pragma unroll
            for (int i = 0; i < 8; i++) ra[i] = As[(ty + 16*i)*PAD + kk];
            #pragma unroll
            for (int j = 0; j < 8; j++) rb[j] = Bs[(tx + 16*j)*PAD + kk];
            #pragma unroll
            for (int i = 0; i < 8; i++)
                #pragma unroll
                for (int j = 0; j < 8; j++) acc[i][j] += ra[i]*rb[j];
        }
        __syncthreads();
    }
    float alpha = 0.f;
    if (EPI == 1) alpha = expf(log_alpha[0]);
    #pragma unroll
    for (int i = 0; i < 8; i++)
        #pragma unroll
        for (int j = 0; j < 8; j++) {
            size_t idx = (size_t)(bm + ty + 16*i)*N + bn + tx + 16*j;
            if (EPI == 0) C[idx] = acc[i][j];
            else          C[idx] = base1[idx] + base2[idx] + alpha*acc[i][j];
        }
}

// ---------------- depthwise causal conv + silu gate -------------------------
__global__ void conv_gate_k(const float* __restrict__ cw, const float* __restrict__ cb) {
    long idx = (long)blockIdx.x*blockDim.x + threadIdx.x;
    if (idx >= (long)BT*DI) return;
    int e = (int)(idx % DI);
    long bl = idx / DI;
    int l = (int)(bl % TT);
    float acc = cb[e];
    #pragma unroll
    for (int j = 0; j < 4; j++) {
        int ll = l - 3 + j;
        if (ll >= 0) acc += g_val[(bl - (3 - j))*DI + e] * cw[e*4 + j];
    }
    float sv = acc / (1.f + expf(-acc));
    float gt = g_gate[idx];
    float sg = gt / (1.f + expf(-gt));
    g_u[idx] = sv * sg;
}

__global__ void zero_w_k() {
    int i = blockIdx.x*blockDim.x + threadIdx.x;
    if (i < BB*DD*DD) g_W[i] = 0.f;
}

// ---------------- scan kernel A: reads[c,dv] = gp[c]*(r@W^T) + (S∘M)@v ------
// grid: 8 batches * 24 dv-tiles of 32
__global__ void __launch_bounds__(256, 2)
attn_read_k(int n, const float* __restrict__ decay_p) {
    const int PAD = 36;
    __shared__ float sA[CH*PAD];   // 128 x 32 (+pad)
    __shared__ float sB[32*PAD];
    int b  = blockIdx.x / 24;
    int j0 = (blockIdx.x % 24) * 32;
    int tid = threadIdx.x;
    int tx = tid & 7, ty = tid >> 3;          // tx: 8 j-groups, ty: 32 c-groups
    float gamma = 1.f / (1.f + expf(-decay_p[0]));
    float lg = logf(gamma);
    float acc[4][4];
    #pragma unroll
    for (int i = 0; i < 4; i++)
        #pragma unroll
        for (int j = 0; j < 4; j++) acc[i][j] = 0.f;

    const float* rbase = g_out + ((size_t)b*TT + (size_t)n*CH)*DD;
    const float* Wbase = g_W + (size_t)b*DD*DD;

    // inter: r[128,768] @ W[j0:j0+32, :]^T
    for (int k0 = 0; k0 < DD; k0 += 32) {
        #pragma unroll
        for (int s = 0; s < 4; s++) {
            int q = tid + 256*s;
            int r = q >> 3, kc = (q & 7) << 2;
            *(float4*)&sA[r*PAD + kc] = *(const float4*)(rbase + (size_t)r*DD + k0 + kc);
        }
        {
            int r = tid >> 3, kc = (tid & 7) << 2;
            *(float4*)&sB[r*PAD + kc] = *(const float4*)(Wbase + (size_t)(j0 + r)*DD + k0 + kc);
        }
        __syncthreads();
        #pragma unroll
        for (int kk = 0; kk < 32; kk++) {
            float ra[4], rb[4];
            #pragma unroll
            for (int i = 0; i < 4; i++) ra[i] = sA[(ty + 32*i)*PAD + kk];
            #pragma unroll
            for (int j = 0; j < 4; j++) rb[j] = sB[(tx + 8*j)*PAD + kk];
            #pragma unroll
            for (int i = 0; i < 4; i++)
                #pragma unroll
                for (int j = 0; j < 4; j++) acc[i][j] += ra[i]*rb[j];
        }
        __syncthreads();
    }
    // scale inter by gp[c] = gamma^c
    #pragma unroll
    for (int i = 0; i < 4; i++) {
        float gp = expf((float)(ty + 32*i) * lg);
        #pragma unroll
        for (int j = 0; j < 4; j++) acc[i][j] *= gp;
    }
    // intra: (S∘M)[128,128] @ v[128, j0:j0+32]
    const float* vbase = g_v + ((size_t)b*TT + (size_t)n*CH)*DD;
    const float* smb = g_SM + b*CH*CH;
    for (int e0 = 0; e0 < CH; e0 += 32) {
        #pragma unroll
        for (int s = 0; s < 4; s++) {
            int q = tid + 256*s;
            int r = q >> 3, kc = (q & 7) << 2;
            *(float4*)&sA[r*PAD + kc] = *(const float4*)(smb + r*CH + e0 + kc);
        }
        {
            int r = tid >> 3, kc = (tid & 7) << 2;
            *(float4*)&sB[r*PAD + kc] = *(const float4*)(vbase + (size_t)(e0 + r)*DD + j0 + kc);
        }
        __syncthreads();
        #pragma unroll
        for (int kk = 0; kk < 32; kk++) {
            float ra[4], rb[4];
            #pragma unroll
            for (int i = 0; i < 4; i++) ra[i] = sA[(ty + 32*i)*PAD + kk];
            #pragma unroll
            for (int j = 0; j < 4; j++) rb[j] = sB[kk*PAD + tx + 8*j];
            #pragma unroll
            for (int i = 0; i < 4; i++)
                #pragma unroll
                for (int j = 0; j < 4; j++) acc[i][j] += ra[i]*rb[j];
        }
        __syncthreads();
    }
    float* ob = g_reads + ((size_t)b*TT + (size_t)n*CH)*DD + j0;
    #pragma unroll
    for (int i = 0; i < 4; i++)
        #pragma unroll
        for (int j = 0; j < 4; j++)
            ob[(size_t)(ty + 32*i)*DD + tx + 8*j] = acc[i][j];
}

// ---------------- scan kernel B: W update (chunk n) + S∘M for chunk n+1 -----
// grid = 8*36 (W tiles) + 8*4 (S tiles) = 320 blocks
__global__ void __launch_bounds__(256, 2)
attn_update_k(int n, const float* __restrict__ decay_p) {
    __shared__ float smem[5760];
    float gamma = 1.f / (1.f + expf(-decay_p[0]));
    float lg = logf(gamma);
    int bid = blockIdx.x;
    int tid = threadIdx.x;

    if (bid < BB*36) {
        if (n < 0) return;
        // part 1: W[b, dv0:+128, dk0:+128] = gamma^128 * W + (v*gw)^T @ k
        int b = bid / 36; int t6 = bid % 36;
        int dv0 = (t6 / 6) * 128, dk0 = (t6 % 6) * 128;
        float* sv = smem;            // [16][132]
        float* sk = smem + 16*132;   // [16][132]
        int tx = tid & 15, ty = tid >> 4;
        float acc[8][8];
        #pragma unroll
        for (int i = 0; i < 8; i++)
            #pragma unroll
            for (int j = 0; j < 8; j++) acc[i][j] = 0.f;
        const float* vb = g_v + ((size_t)b*TT + (size_t)n*CH)*DD;
        const float* ob = g_out + (size_t)b*TT*DD;
        int tbase = n*CH;
        for (int c0 = 0; c0 < CH; c0 += 16) {
            #pragma unroll
            for (int s = 0; s < 2; s++) {
                int q = tid + 256*s;
                int cc = q >> 5, col = (q & 31) << 2;
                int c = c0 + cc;
                float gw = expf((float)(CH - 1 - c) * lg);
                float4 vv = *(const float4*)(vb + (size_t)c*DD + dv0 + col);
                vv.x *= gw; vv.y *= gw; vv.z *= gw; vv.w *= gw;
                *(float4*)&sv[cc*132 + col] = vv;
                int t = tbase + c;
                float4 kv;
                if (t == 0) { kv.x = kv.y = kv.z = kv.w = 0.f; }
                else kv = *(const float4*)(ob + (size_t)(t - 1)*DD + dk0 + col);
                *(float4*)&sk[cc*132 + col] = kv;
            }
            __syncthreads();
            #pragma unroll
            for (int cc = 0; cc < 16; cc++) {
                float ra[8], rb[8];
                #pragma unroll
                for (int i = 0; i < 8; i++) ra[i] = sv[cc*132 + ty + 16*i];
                #pragma unroll
                for (int j = 0; j < 8; j++) rb[j] = sk[cc*132 + tx + 16*j];
                #pragma unroll
                for (int i = 0; i < 8; i++)
                    #pragma unroll
                    for (int j = 0; j < 8; j++) acc[i][j] += ra[i]*rb[j];
            }
            __syncthreads();
        }
        float gC = expf((float)CH * lg);
        float* Wb = g_W + (size_t)b*DD*DD;
        #pragma unroll
        for (int i = 0; i < 8; i++)
            #pragma unroll
            for (int j = 0; j < 8; j++) {
                size_t idx = (size_t)(dv0 + ty + 16*i)*DD + dk0 + tx + 16*j;
                Wb[idx] = gC*Wb[idx] + acc[i][j];
            }
    } else {
        // part 2: S∘M for chunk m = n+1 : SM[c,e] = mask * gamma^(c-1-e) * (r_c . k_e)
        int m = n + 1;
        if (m >= NCH) return;
        const int PAD = 36;
        int q = bid - BB*36;
        int b = q / 4; int c0 = (q % 4) * 32;
        float* sK = smem;            // [128][36] — keys (shifted out)
        float* sR = smem + CH*PAD;   // [32][36]  — queries r
        int tx = tid & 7, ty = tid >> 3;
        float acc[4][4];
        #pragma unroll
        for (int i = 0; i < 4; i++)
            #pragma unroll
            for (int j = 0; j < 4; j++) acc[i][j] = 0.f;
        const float* ob = g_out + (size_t)b*TT*DD;
        int tbase = m*CH;
        for (int k0 = 0; k0 < DD; k0 += 32) {
            #pragma unroll
            for (int s = 0; s < 4; s++) {
                int q2 = tid + 256*s;
                int r = q2 >> 3, kc = (q2 & 7) << 2;
                int t = tbase + r;
                float4 kv;
                if (t == 0) { kv.x = kv.y = kv.z = kv.w = 0.f; }
                else kv = *(const float4*)(ob + (size_t)(t - 1)*DD + k0 + kc);
                *(float4*)&sK[r*PAD + kc] = kv;
            }
            {
                int r = tid >> 3, kc = (tid & 7) << 2;
                *(float4*)&sR[r*PAD + kc] =
                    *(const float4*)(ob + (size_t)(tbase + c0 + r)*DD + k0 + kc);
            }
            __syncthreads();
            #pragma unroll
            for (int kk = 0; kk < 32; kk++) {
                float ra[4], rb[4];
                #pragma unroll
                for (int i = 0; i < 4; i++) ra[i] = sK[(ty + 32*i)*PAD + kk];
                #pragma unroll
                for (int j = 0; j < 4; j++) rb[j] = sR[(tx + 8*j)*PAD + kk];
                #pragma unroll
                for (int i = 0; i < 4; i++)
                    #pragma unroll
                    for (int j = 0; j < 4; j++) acc[i][j] += ra[i]*rb[j];
            }
            __syncthreads();
        }
        float* smb = g_SM + b*CH*CH;
        #pragma unroll
        for (int i = 0; i < 4; i++) {
            int e = ty + 32*i;
            #pragma unroll
            for (int j = 0; j < 4; j++) {
                int c = c0 + tx + 8*j;
                float vv = (c > e) ? expf((float)(c - 1 - e) * lg) * acc[i][j] : 0.f;
                smb[c*CH + e] = vv;
            }
        }
    }
}

// ---------------- launch ----------------------------------------------------
extern "C" void kernel_launch(void* const* d_in, const int* in_sizes, int n_in,
                              void* d_out, int out_size) {
    const float* x          = (const float*)d_in[0];
    const float* norm_w     = (const float*)d_in[1];
    const float* proj_w     = (const float*)d_in[2];
    const float* gate_w     = (const float*)d_in[3];
    const float* conv_w     = (const float*)d_in[4];
    const float* conv_b     = (const float*)d_in[5];
    const float* out_proj_w = (const float*)d_in[6];
    const float* write_w    = (const float*)d_in[7];
    const float* read_w     = (const float*)d_in[8];
    const float* decay      = (const float*)d_in[9];
    const float* log_alpha  = (const float*)d_in[10];
    float* out = (float*)d_out;

    float *xn, *val, *gate, *u, *o, *v, *reads;
    cudaGetSymbolAddress((void**)&xn,    g_xn);
    cudaGetSymbolAddress((void**)&val,   g_val);
    cudaGetSymbolAddress((void**)&gate,  g_gate);
    cudaGetSymbolAddress((void**)&u,     g_u);
    cudaGetSymbolAddress((void**)&o,     g_out);
    cudaGetSymbolAddress((void**)&v,     g_v);
    cudaGetSymbolAddress((void**)&reads, g_reads);

    // 1. rmsnorm
    rmsnorm_k<<<BT, 256>>>(x, norm_w);
    // 2. proj / gate GEMMs: [32768,768] x [1536,768]^T
    dim3 g1(DI/128, BT/128);
    gemm_nt<0><<<g1, 256>>>(xn, proj_w, val,  BT, DI, DD, nullptr, nullptr, nullptr);
    gemm_nt<0><<<g1, 256>>>(xn, gate_w, gate, BT, DI, DD, nullptr, nullptr, nullptr);
    // 3. causal depthwise conv + silu * silu(gate)
    long ne = (long)BT*DI;
    conv_gate_k<<<(unsigned)((ne + 255)/256), 256>>>(conv_w, conv_b);
    // 4. out projection: [32768,1536] x [768,1536]^T
    dim3 g2(DD/128, BT/128);
    gemm_nt<0><<<g2, 256>>>(u, out_proj_w, o, BT, DD, DI, nullptr, nullptr, nullptr);
    // 5. write projection: v = out @ write_w^T
    gemm_nt<0><<<g2, 256>>>(o, write_w, v, BT, DD, DD, nullptr, nullptr, nullptr);
    // 6. scan init: W = 0, S∘M for chunk 0
    zero_w_k<<<(BB*DD*DD + 255)/256, 256>>>();
    attn_update_k<<<320, 256>>>(-1, decay);
    // 7. chunk scan (C'=128, 32 steps): reads(n) uses W<n; update builds W<=n and S(n+1)
    for (int n = 0; n < NCH; n++) {
        attn_read_k<<<192, 256>>>(n, decay);
        if (n < NCH - 1) attn_update_k<<<320, 256>>>(n, decay);
    }
    // 8. final: out = x + o + exp(log_alpha) * (reads @ read_w^T)
    gemm_nt<1><<<g2, 256>>>(reads, read_w, out, BT, DD, DD, x, o, log_alpha);
}

// round 2
// speedup vs baseline: 5.0815x; 5.0815x over previous
#include <cuda_runtime.h>
#include <math.h>

#define BB 8
#define TT 4096
#define DD 768
#define DI 1536
#define BT (BB*TT)
#define CH 128
#define NCH 32
#define EPS 1e-5f

// ---------------- scratch (device globals) ----------------------------------
__device__ float g_xn[(size_t)BT*DD];
__device__ float g_val[(size_t)BT*DI];
__device__ float g_gate[(size_t)BT*DI];
__device__ float g_u[(size_t)BT*DI];
__device__ float g_out[(size_t)BT*DD];
__device__ float g_v[(size_t)BT*DD];
__device__ float g_reads[(size_t)BT*DD];
__device__ float g_Wb[(size_t)(NCH-1)*BB*DD*DD];   // slot s: U_s, then after scan W_{s+1}
__device__ float g_SM[(size_t)BB*NCH*CH*CH];       // masked decay-weighted S per chunk

// ---------------- tf32 mma helpers ------------------------------------------
__device__ __forceinline__ unsigned f2tf(float x){
    unsigned u; asm("cvt.rna.tf32.f32 %0, %1;" : "=r"(u) : "f"(x)); return u;
}
__device__ __forceinline__ void mma8(float* c, const unsigned* a, const unsigned* b){
    asm volatile("mma.sync.aligned.m16n8k8.row.col.f32.tf32.tf32.f32 "
        "{%0,%1,%2,%3}, {%4,%5,%6,%7}, {%8,%9}, {%0,%1,%2,%3};"
        : "+f"(c[0]), "+f"(c[1]), "+f"(c[2]), "+f"(c[3])
        : "r"(a[0]), "r"(a[1]), "r"(a[2]), "r"(a[3]), "r"(b[0]), "r"(b[1]));
}

#define SMM 36    // m-major smem stride (32 + 4 pad)  -> frag addr mod32 = 4*gid+tg
#define SKM 132   // k-major smem stride (128 + 4 pad) -> frag addr mod32 = 4*tg+gid

// block = 256 thr = 8 warps as 2(m) x 4(n); warp tile 64x32; 4x4 frags of m16n8k8
template<int AKM, int BKM>
__device__ __forceinline__ void mma_tile(const unsigned* As, const unsigned* Bs,
                                         float (&acc)[4][4][4], int lane, int wm, int wn){
    int tg = lane & 3, gid = lane >> 2;
    #pragma unroll
    for (int kk = 0; kk < 32; kk += 8){
        unsigned a[4][4], b[4][2];
        #pragma unroll
        for (int mi = 0; mi < 4; mi++){
            int row = wm*64 + mi*16 + gid;
            if (AKM){
                a[mi][0] = As[(kk+tg)*SKM + row];
                a[mi][1] = As[(kk+tg)*SKM + row + 8];
                a[mi][2] = As[(kk+tg+4)*SKM + row];
                a[mi][3] = As[(kk+tg+4)*SKM + row + 8];
            } else {
                a[mi][0] = As[row*SMM + kk+tg];
                a[mi][1] = As[(row+8)*SMM + kk+tg];
                a[mi][2] = As[row*SMM + kk+tg+4];
                a[mi][3] = As[(row+8)*SMM + kk+tg+4];
            }
        }
        #pragma unroll
        for (int ni = 0; ni < 4; ni++){
            int col = wn*32 + ni*8 + gid;
            if (BKM){
                b[ni][0] = Bs[(kk+tg)*SKM + col];
                b[ni][1] = Bs[(kk+tg+4)*SKM + col];
            } else {
                b[ni][0] = Bs[col*SMM + kk+tg];
                b[ni][1] = Bs[col*SMM + kk+tg+4];
            }
        }
        #pragma unroll
        for (int mi = 0; mi < 4; mi++)
            #pragma unroll
            for (int ni = 0; ni < 4; ni++)
                mma8(acc[mi][ni], a[mi], b[ni]);
    }
}

// 128 rows x 32 k from row-major src (ld), into m-major smem
__device__ __forceinline__ void ld_mm(unsigned* S, const float* src, size_t ld, int tid){
    #pragma unroll
    for (int s = 0; s < 4; s++){
        int q = tid + 256*s; int r = q>>3, kc = (q&7)<<2;
        float4 v = *(const float4*)(src + (size_t)r*ld + kc);
        unsigned* d = S + r*SMM + kc;
        d[0]=f2tf(v.x); d[1]=f2tf(v.y); d[2]=f2tf(v.z); d[3]=f2tf(v.w);
    }
}
// 32 k-rows x 128 cols from row-major src (ld), into k-major smem
__device__ __forceinline__ void ld_km(unsigned* S, const float* src, size_t ld, int tid){
    #pragma unroll
    for (int s = 0; s < 4; s++){
        int q = tid + 256*s; int kk = q>>5, nc = (q&31)<<2;
        float4 v = *(const float4*)(src + (size_t)kk*ld + nc);
        unsigned* d = S + kk*SKM + nc;
        d[0]=f2tf(v.x); d[1]=f2tf(v.y); d[2]=f2tf(v.z); d[3]=f2tf(v.w);
    }
}

// ---------------- rmsnorm ---------------------------------------------------
__global__ void rmsnorm_k(const float* __restrict__ x, const float* __restrict__ w) {
    int row = blockIdx.x;
    const float* xr = x + (size_t)row*DD;
    float* o = g_xn + (size_t)row*DD;
    float s = 0.f;
    for (int d = threadIdx.x; d < DD; d += blockDim.x) { float v = xr[d]; s += v*v; }
    __shared__ float red[32];
    for (int off = 16; off; off >>= 1) s += __shfl_down_sync(0xffffffffu, s, off);
    if ((threadIdx.x & 31) == 0) red[threadIdx.x >> 5] = s;
    __syncthreads();
    if (threadIdx.x < 32) {
        float t = (threadIdx.x < (blockDim.x >> 5)) ? red[threadIdx.x] : 0.f;
        for (int off = 16; off; off >>= 1) t += __shfl_down_sync(0xffffffffu, t, off);
        if (threadIdx.x == 0) red[0] = t;
    }
    __syncthreads();
    float scale = rsqrtf(red[0] / (float)DD + EPS);
    for (int d = threadIdx.x; d < DD; d += blockDim.x) o[d] = xr[d] * scale * w[d];
}

// ---------------- big GEMM: C[M,N] = A[M,K] @ Bw[N,K]^T (tf32 TC) -----------
template<int EPI>
__global__ void __launch_bounds__(256)
gemm_tc(const float* __restrict__ A, const float* __restrict__ Bw,
        float* __restrict__ C, int M, int N, int K,
        const float* __restrict__ base1, const float* __restrict__ base2,
        const float* __restrict__ log_alpha)
{
    __shared__ unsigned As[128*SMM], Bs[128*SMM];
    int bm = blockIdx.y*128, bn = blockIdx.x*128;
    int tid = threadIdx.x, lane = tid&31, warp = tid>>5;
    int wm = warp>>2, wn = warp&3;
    float acc[4][4][4];
    #pragma unroll
    for (int i=0;i<4;i++){ 
        #pragma unroll
        for(int j=0;j<4;j++){
            #pragma unroll
            for(int q=0;q<4;q++) acc[i][j][q]=0.f;
        }
    }
    for (int k0 = 0; k0 < K; k0 += 32){
        ld_mm(As, A  + (size_t)bm*K + k0, K, tid);
        ld_mm(Bs, Bw + (size_t)bn*K + k0, K, tid);
        __syncthreads();
        mma_tile<0,0>(As, Bs, acc, lane, wm, wn);
        __syncthreads();
    }
    int tg = lane&3, gid = lane>>2;
    float alpha = (EPI==1) ? expf(log_alpha[0]) : 0.f;
    #pragma unroll
    for (int mi=0;mi<4;mi++){
        #pragma unroll
        for (int ni=0;ni<4;ni++){
            int row = bm + wm*64 + mi*16 + gid;
            int col = bn + wn*32 + ni*8 + 2*tg;
            size_t i0 = (size_t)row*N + col;
            size_t i1 = (size_t)(row+8)*N + col;
            if (EPI==0){
                *(float2*)(C+i0) = make_float2(acc[mi][ni][0], acc[mi][ni][1]);
                *(float2*)(C+i1) = make_float2(acc[mi][ni][2], acc[mi][ni][3]);
            } else {
                float2 x0 = *(const float2*)(base1+i0), o0 = *(const float2*)(base2+i0);
                float2 x1 = *(const float2*)(base1+i1), o1 = *(const float2*)(base2+i1);
                *(float2*)(C+i0) = make_float2(x0.x+o0.x+alpha*acc[mi][ni][0],
                                               x0.y+o0.y+alpha*acc[mi][ni][1]);
                *(float2*)(C+i1) = make_float2(x1.x+o1.x+alpha*acc[mi][ni][2],
                                               x1.y+o1.y+alpha*acc[mi][ni][3]);
            }
        }
    }
}

// ---------------- depthwise causal conv + silu gate -------------------------
__global__ void conv_gate_k(const float* __restrict__ cw, const float* __restrict__ cb) {
    long idx = (long)blockIdx.x*blockDim.x + threadIdx.x;
    if (idx >= (long)BT*DI) return;
    int e = (int)(idx % DI);
    long bl = idx / DI;
    int l = (int)(bl % TT);
    float acc = cb[e];
    #pragma unroll
    for (int j = 0; j < 4; j++) {
        int ll = l - 3 + j;
        if (ll >= 0) acc += g_val[(bl - (3 - j))*DI + e] * cw[e*4 + j];
    }
    float sv = acc / (1.f + expf(-acc));
    float gt = g_gate[idx];
    float sg = gt / (1.f + expf(-gt));
    g_u[idx] = sv * sg;
}

// ---------------- batched U_m = (v*gw)^T @ k (all chunks parallel) ----------
__global__ void __launch_bounds__(256)
u_batch_k(const float* __restrict__ decay_p){
    __shared__ unsigned As[32*SKM], Bs[32*SKM];
    int z = blockIdx.z, b = z/(NCH-1), mch = z%(NCH-1);
    int bm = blockIdx.y*128, bn = blockIdx.x*128;
    int tid=threadIdx.x, lane=tid&31, warp=tid>>5, wm=warp>>2, wn=warp&3;
    float gamma = 1.f/(1.f+expf(-decay_p[0]));
    float lg = logf(gamma);
    float acc[4][4][4];
    #pragma unroll
    for (int i=0;i<4;i++){ 
        #pragma unroll
        for(int j=0;j<4;j++){ 
            #pragma unroll
            for(int q=0;q<4;q++) acc[i][j][q]=0.f; } }
    const float* vb = g_v   + ((size_t)b*TT + (size_t)mch*CH)*DD;
    const float* kb = g_out + ((size_t)b*TT + (size_t)mch*CH)*DD;
    for (int c0 = 0; c0 < CH; c0 += 32){
        #pragma unroll
        for (int s=0;s<4;s++){              // A: v rows (k-major), scaled by gw(c)
            int q = tid+256*s; int kk=q>>5, mc=(q&31)<<2;
            int c = c0+kk;
            float gw = expf((float)(CH-1-c)*lg);
            float4 vv = *(const float4*)(vb + (size_t)c*DD + bm + mc);
            unsigned* d = As + kk*SKM + mc;
            d[0]=f2tf(vv.x*gw); d[1]=f2tf(vv.y*gw); d[2]=f2tf(vv.z*gw); d[3]=f2tf(vv.w*gw);
        }
        #pragma unroll
        for (int s=0;s<4;s++){              // B: shifted keys (k-major)
            int q = tid+256*s; int kk=q>>5, nc=(q&31)<<2;
            int c = c0+kk;
            float4 kv;
            if (mch==0 && c==0) kv = make_float4(0.f,0.f,0.f,0.f);
            else kv = *(const float4*)(kb + (size_t)(c-1)*DD + bn + nc);
            unsigned* d = Bs + kk*SKM + nc;
            d[0]=f2tf(kv.x); d[1]=f2tf(kv.y); d[2]=f2tf(kv.z); d[3]=f2tf(kv.w);
        }
        __syncthreads();
        mma_tile<1,1>(As, Bs, acc, lane, wm, wn);
        __syncthreads();
    }
    float* Wout = g_Wb + ((size_t)mch*BB + b)*DD*DD;
    int tg=lane&3, gid=lane>>2;
    #pragma unroll
    for (int mi=0;mi<4;mi++){
        #pragma unroll
        for (int ni=0;ni<4;ni++){
            int row = bm + wm*64 + mi*16 + gid;
            int col = bn + wn*32 + ni*8 + 2*tg;
            *(float2*)(Wout + (size_t)row*DD + col)     = make_float2(acc[mi][ni][0], acc[mi][ni][1]);
            *(float2*)(Wout + (size_t)(row+8)*DD + col) = make_float2(acc[mi][ni][2], acc[mi][ni][3]);
        }
    }
}

// ---------------- serial AXPY scan over slots: slot[s] += gamma^128*slot[s-1]
__global__ void wscan_k(int s, const float* __restrict__ decay_p){
    const size_t n = (size_t)BB*DD*DD;
    size_t i = ((size_t)blockIdx.x*256 + threadIdx.x)*4;
    if (i >= n) return;
    float gamma = 1.f/(1.f+expf(-decay_p[0]));
    float gC = expf(128.f*logf(gamma));
    float4* cur = (float4*)(g_Wb + (size_t)s*n + i);
    float4 p = *(const float4*)(g_Wb + (size_t)(s-1)*n + i);
    float4 c = *cur;
    c.x += gC*p.x; c.y += gC*p.y; c.z += gC*p.z; c.w += gC*p.w;
    *cur = c;
}

// ---------------- batched masked S: SM[c,e] = (c>e) g^(c-1-e) (r_c.k_e) -----
__global__ void __launch_bounds__(256)
s_batch_k(const float* __restrict__ decay_p){
    __shared__ unsigned As[128*SMM], Bs[128*SMM];
    int z = blockIdx.x, b = z/NCH, n = z%NCH;
    int tid=threadIdx.x, lane=tid&31, warp=tid>>5, wm=warp>>2, wn=warp&3;
    float acc[4][4][4];
    #pragma unroll
    for (int i=0;i<4;i++){ 
        #pragma unroll
        for(int j=0;j<4;j++){ 
            #pragma unroll
            for(int q=0;q<4;q++) acc[i][j][q]=0.f; } }
    const float* rb = g_out + ((size_t)b*TT + (size_t)n*CH)*DD;
    for (int k0 = 0; k0 < DD; k0 += 32){
        ld_mm(As, rb + k0, DD, tid);
        #pragma unroll
        for (int s=0;s<4;s++){              // B: shifted keys, m-major
            int q = tid+256*s; int e=q>>3, kc=(q&7)<<2;
            float4 v;
            if (n==0 && e==0) v = make_float4(0.f,0.f,0.f,0.f);
            else v = *(const float4*)(rb + (size_t)(e-1)*DD + k0 + kc);
            unsigned* d = Bs + e*SMM + kc;
            d[0]=f2tf(v.x); d[1]=f2tf(v.y); d[2]=f2tf(v.z); d[3]=f2tf(v.w);
        }
        __syncthreads();
        mma_tile<0,0>(As, Bs, acc, lane, wm, wn);
        __syncthreads();
    }
    float gamma = 1.f/(1.f+expf(-decay_p[0]));
    float lg = logf(gamma);
    float* smb = g_SM + ((size_t)b*NCH + n)*CH*CH;
    int tg=lane&3, gid=lane>>2;
    #pragma unroll
    for (int mi=0;mi<4;mi++){
        #pragma unroll
        for (int ni=0;ni<4;ni++){
            int c0r = wm*64 + mi*16 + gid;
            int e0c = wn*32 + ni*8 + 2*tg;
            #pragma unroll
            for (int q=0;q<4;q++){
                int c = c0r + ((q>=2)?8:0);
                int e = e0c + (q&1);
                float v = (c>e) ? expf((float)(c-1-e)*lg)*acc[mi][ni][q] : 0.f;
                smb[(size_t)c*CH + e] = v;
            }
        }
    }
}

// ---------------- batched intra: reads = SM @ v (writes) --------------------
__global__ void __launch_bounds__(256)
intra_k(){
    __shared__ unsigned As[128*SMM], Bs[32*SKM];
    int z = blockIdx.z, b = z/NCH, n = z%NCH;
    int bn = blockIdx.x*128;
    int tid=threadIdx.x, lane=tid&31, warp=tid>>5, wm=warp>>2, wn=warp&3;
    float acc[4][4][4];
    #pragma unroll
    for (int i=0;i<4;i++){ 
        #pragma unroll
        for(int j=0;j<4;j++){ 
            #pragma unroll
            for(int q=0;q<4;q++) acc[i][j][q]=0.f; } }
    const float* smb = g_SM + ((size_t)b*NCH+n)*CH*CH;
    const float* vb  = g_v  + ((size_t)b*TT + (size_t)n*CH)*DD;
    for (int e0=0;e0<CH;e0+=32){
        ld_mm(As, smb + e0, CH, tid);
        ld_km(Bs, vb + (size_t)e0*DD + bn, DD, tid);
        __syncthreads();
        mma_tile<0,1>(As, Bs, acc, lane, wm, wn);
        __syncthreads();
    }
    float* ob = g_reads + ((size_t)b*TT + (size_t)n*CH)*DD + bn;
    int tg=lane&3, gid=lane>>2;
    #pragma unroll
    for (int mi=0;mi<4;mi++){
        #pragma unroll
        for (int ni=0;ni<4;ni++){
            int row = wm*64 + mi*16 + gid;
            int col = wn*32 + ni*8 + 2*tg;
            *(float2*)(ob + (size_t)row*DD + col)     = make_float2(acc[mi][ni][0], acc[mi][ni][1]);
            *(float2*)(ob + (size_t)(row+8)*DD + col) = make_float2(acc[mi][ni][2], acc[mi][ni][3]);
        }
    }
}

// ---------------- batched inter: reads += gp[c] * (r @ W_n^T) ---------------
__global__ void __launch_bounds__(256)
inter_k(const float* __restrict__ decay_p){
    __shared__ unsigned As[128*SMM], Bs[128*SMM];
    int z = blockIdx.z, b = z/(NCH-1), n = z%(NCH-1) + 1;
    int bn = blockIdx.x*128;
    int tid=threadIdx.x, lane=tid&31, warp=tid>>5, wm=warp>>2, wn=warp&3;
    float acc[4][4][4];
    #pragma unroll
    for (int i=0;i<4;i++){ 
        #pragma unroll
        for(int j=0;j<4;j++){ 
            #pragma unroll
            for(int q=0;q<4;q++) acc[i][j][q]=0.f; } }
    const float* rb = g_out + ((size_t)b*TT + (size_t)n*CH)*DD;
    const float* Wb = g_Wb + ((size_t)(n-1)*BB + b)*DD*DD;
    for (int k0=0;k0<DD;k0+=32){
        ld_mm(As, rb + k0, DD, tid);
        ld_mm(Bs, Wb + (size_t)bn*DD + k0, DD, tid);
        __syncthreads();
        mma_tile<0,0>(As, Bs, acc, lane, wm, wn);
        __syncthreads();
    }
    float gamma = 1.f/(1.f+expf(-decay_p[0]));
    float lg = logf(gamma);
    float* ob = g_reads + ((size_t)b*TT + (size_t)n*CH)*DD + bn;
    int tg=lane&3, gid=lane>>2;
    #pragma unroll
    for (int mi=0;mi<4;mi++){
        int row = wm*64+mi*16+gid;
        float s0 = expf((float)row*lg);
        float s1 = expf((float)(row+8)*lg);
        #pragma unroll
        for (int ni=0;ni<4;ni++){
            int col = wn*32+ni*8+2*tg;
            float2* p0 = (float2*)(ob + (size_t)row*DD + col);
            float2* p1 = (float2*)(ob + (size_t)(row+8)*DD + col);
            float2 a0 = *p0, a1 = *p1;
            a0.x += s0*acc[mi][ni][0]; a0.y += s0*acc[mi][ni][1];
            a1.x += s1*acc[mi][ni][2]; a1.y += s1*acc[mi][ni][3];
            *p0 = a0; *p1 = a1;
        }
    }
}

// ---------------- launch ----------------------------------------------------
extern "C" void kernel_launch(void* const* d_in, const int* in_sizes, int n_in,
                              void* d_out, int out_size) {
    const float* x          = (const float*)d_in[0];
    const float* norm_w     = (const float*)d_in[1];
    const float* proj_w     = (const float*)d_in[2];
    const float* gate_w     = (const float*)d_in[3];
    const float* conv_w     = (const float*)d_in[4];
    const float* conv_b     = (const float*)d_in[5];
    const float* out_proj_w = (const float*)d_in[6];
    const float* write_w    = (const float*)d_in[7];
    const float* read_w     = (const float*)d_in[8];
    const float* decay      = (const float*)d_in[9];
    const float* log_alpha  = (const float*)d_in[10];
    float* out = (float*)d_out;

    float *xn, *val, *gate, *u, *o, *v, *reads;
    cudaGetSymbolAddress((void**)&xn,    g_xn);
    cudaGetSymbolAddress((void**)&val,   g_val);
    cudaGetSymbolAddress((void**)&gate,  g_gate);
    cudaGetSymbolAddress((void**)&u,     g_u);
    cudaGetSymbolAddress((void**)&o,     g_out);
    cudaGetSymbolAddress((void**)&v,     g_v);
    cudaGetSymbolAddress((void**)&reads, g_reads);

    // 1. rmsnorm
    rmsnorm_k<<<BT, 256>>>(x, norm_w);
    // 2. proj / gate GEMMs (tf32 TC)
    dim3 g1(DI/128, BT/128);
    gemm_tc<0><<<g1, 256>>>(xn, proj_w, val,  BT, DI, DD, nullptr, nullptr, nullptr);
    gemm_tc<0><<<g1, 256>>>(xn, gate_w, gate, BT, DI, DD, nullptr, nullptr, nullptr);
    // 3. conv + gate
    long ne = (long)BT*DI;
    conv_gate_k<<<(unsigned)((ne + 255)/256), 256>>>(conv_w, conv_b);
    // 4. out projection + write projection
    dim3 g2(DD/128, BT/128);
    gemm_tc<0><<<g2, 256>>>(u, out_proj_w, o, BT, DD, DI, nullptr, nullptr, nullptr);
    gemm_tc<0><<<g2, 256>>>(o, write_w, v, BT, DD, DD, nullptr, nullptr, nullptr);
    // 5. all chunk outer products U_m (parallel), then 30-step AXPY scan
    u_batch_k<<<dim3(6,6,BB*(NCH-1)), 256>>>(decay);
    for (int s = 1; s < NCH-1; s++)
        wscan_k<<<4608, 256>>>(s, decay);
    // 6. masked S (parallel), intra reads (parallel write), inter reads (accumulate)
    s_batch_k<<<BB*NCH, 256>>>(decay);
    intra_k<<<dim3(6,1,BB*NCH), 256>>>();
    inter_k<<<dim3(6,1,BB*(NCH-1)), 256>>>(decay);
    // 7. final: out = x + o + exp(log_alpha) * (reads @ read_w^T)
    gemm_tc<1><<<g2, 256>>>(reads, read_w, out, BT, DD, DD, x, o, log_alpha);
}

// round 6
// speedup vs baseline: 6.8304x; 1.3442x over previous
#include <cuda_runtime.h>
#include <cuda_fp16.h>
#include <math.h>
#include <stdint.h>

#define BB 8
#define TT 4096
#define DD 768
#define DI 1536
#define BT (BB*TT)
#define CH 128
#define NCH 32
#define EPS 1e-5f

// ---------------- scratch (device globals) ----------------------------------
__device__ __half g_xnh[(size_t)BT*DD];
__device__ __half g_valh[(size_t)BT*DI];
__device__ __half g_gateh[(size_t)BT*DI];
__device__ __half g_uh[(size_t)BT*DI];
__device__ __half g_oh[(size_t)BT*DD];
__device__ __half g_readsh[(size_t)BT*DD];
__device__ __half g_wth[4718592];                  // fp16 weights
__device__ float g_out[(size_t)BT*DD];             // conv-mix out (fp32, scan + residual)
__device__ float g_v[(size_t)BT*DD];               // write projection (fp32, scan)
__device__ float g_reads[(size_t)BT*DD];           // attention reads (fp32)
__device__ float g_Wb[(size_t)(NCH-1)*BB*DD*DD];   // slot s: U_s -> after scan W_{s+1}
__device__ float g_SM[(size_t)BB*NCH*CH*CH];

#define W_PROJ 0
#define W_GATE 1179648
#define W_OUTP 2359296
#define W_WRIT 3538944
#define W_READ 4128768

// ---------------- small helpers ---------------------------------------------
__device__ __forceinline__ unsigned f2tf(float x){
    unsigned u; asm("cvt.rna.tf32.f32 %0, %1;" : "=r"(u) : "f"(x)); return u;
}
__device__ __forceinline__ unsigned smem_u32(const void* p){
    return (unsigned)__cvta_generic_to_shared(p);
}
__device__ __forceinline__ void cpa16(unsigned s, const void* g){
    asm volatile("cp.async.cg.shared.global [%0], [%1], 16;" :: "r"(s), "l"(g));
}

// ================= fp16 legacy-TC GEMM: C[M,N]=A[M,K]@B[N,K]^T ==============
// 256 thr, tile 128x128, K-tile 32, double-buffered cp.async.
// smem row layout: 16 half2 per 32-k row + 4 pad (stride 20 words) — fragment
// loads (addr = row*20 + kk2 + tg) are bank-conflict-free.
#define SMH 20

__device__ __forceinline__ void mma16(float* c, const unsigned* a, const unsigned* b){
    asm volatile("mma.sync.aligned.m16n8k16.row.col.f32.f16.f16.f32 "
        "{%0,%1,%2,%3}, {%4,%5,%6,%7}, {%8,%9}, {%0,%1,%2,%3};"
        : "+f"(c[0]), "+f"(c[1]), "+f"(c[2]), "+f"(c[3])
        : "r"(a[0]), "r"(a[1]), "r"(a[2]), "r"(a[3]), "r"(b[0]), "r"(b[1]));
}

__device__ __forceinline__ void ldh(unsigned* S, const __half* src, int ldk, int tid){
    unsigned sb = smem_u32(S);
    #pragma unroll
    for (int s = 0; s < 2; s++){
        int q = tid + 256*s;              // 512 x 16B chunks = 128 rows x 32 halfs
        int r = q>>2, kc8 = (q&3)<<3;
        cpa16(sb + (unsigned)(r*SMH + (kc8>>1))*4u, src + (size_t)r*ldk + kc8);
    }
}

__device__ __forceinline__ void mma_tile_h(const unsigned* As, const unsigned* Bs,
                                           float (&acc)[4][4][4], int lane, int wm, int wn){
    int tg = lane & 3, gid = lane >> 2;
    #pragma unroll
    for (int kk2 = 0; kk2 < 16; kk2 += 8){
        unsigned a[4][4], b[4][2];
        #pragma unroll
        for (int mi = 0; mi < 4; mi++){
            int row = wm*64 + mi*16 + gid;
            a[mi][0] = As[row*SMH + kk2 + tg];
            a[mi][1] = As[(row+8)*SMH + kk2 + tg];
            a[mi][2] = As[row*SMH + kk2 + tg + 4];
            a[mi][3] = As[(row+8)*SMH + kk2 + tg + 4];
        }
        #pragma unroll
        for (int ni = 0; ni < 4; ni++){
            int col = wn*32 + ni*8 + gid;
            b[ni][0] = Bs[col*SMH + kk2 + tg];
            b[ni][1] = Bs[col*SMH + kk2 + tg + 4];
        }
        #pragma unroll
        for (int mi = 0; mi < 4; mi++)
            #pragma unroll
            for (int ni = 0; ni < 4; ni++)
                mma16(acc[mi][ni], a[mi], b[ni]);
    }
}

// EPI: 0 fp32 store; 1 final (base1+base2+alpha*acc, fp32); 5 half store; 6 dual
template<int EPI>
__global__ void __launch_bounds__(256)
gemm_h(const __half* __restrict__ A, const __half* __restrict__ Bw,
       float* __restrict__ C, __half* __restrict__ Ch, int K, int N,
       const float* __restrict__ base1, const float* __restrict__ base2,
       const float* __restrict__ sp)
{
    __shared__ unsigned As[2][128*SMH], Bs[2][128*SMH];
    int bm = blockIdx.y*128, bn = blockIdx.x*128;
    int tid = threadIdx.x, lane = tid&31, warp = tid>>5;
    int wm = warp>>2, wn = warp&3;
    float acc[4][4][4];
    #pragma unroll
    for (int i=0;i<4;i++)
        #pragma unroll
        for(int j=0;j<4;j++)
            #pragma unroll
            for(int q=0;q<4;q++) acc[i][j][q]=0.f;

    const __half* Ag = A + (size_t)bm*K;
    const __half* Bg = Bw + (size_t)bn*K;
    int nk = K >> 5;

    ldh(As[0], Ag, K, tid);
    ldh(Bs[0], Bg, K, tid);
    asm volatile("cp.async.commit_group;" ::: "memory");

    for (int t = 0; t < nk; t++){
        int cur = t & 1;
        if (t + 1 < nk){
            ldh(As[cur^1], Ag + (t+1)*32, K, tid);
            ldh(Bs[cur^1], Bg + (t+1)*32, K, tid);
            asm volatile("cp.async.commit_group;" ::: "memory");
            asm volatile("cp.async.wait_group 1;" ::: "memory");
        } else {
            asm volatile("cp.async.wait_group 0;" ::: "memory");
        }
        __syncthreads();
        mma_tile_h(As[cur], Bs[cur], acc, lane, wm, wn);
        __syncthreads();
    }

    int tg = lane&3, gid = lane>>2;
    float alpha = (EPI==1) ? expf(sp[0]) : 0.f;
    #pragma unroll
    for (int mi=0;mi<4;mi++){
        #pragma unroll
        for (int ni=0;ni<4;ni++){
            int row = bm + wm*64 + mi*16 + gid;
            int col = bn + wn*32 + ni*8 + 2*tg;
            size_t i0 = (size_t)row*N + col;
            size_t i1 = (size_t)(row+8)*N + col;
            float a0 = acc[mi][ni][0], a1 = acc[mi][ni][1];
            float a2 = acc[mi][ni][2], a3 = acc[mi][ni][3];
            if (EPI == 0){
                *(float2*)(C+i0) = make_float2(a0, a1);
                *(float2*)(C+i1) = make_float2(a2, a3);
            } else if (EPI == 5){
                *(__half2*)(Ch+i0) = __floats2half2_rn(a0, a1);
                *(__half2*)(Ch+i1) = __floats2half2_rn(a2, a3);
            } else if (EPI == 6){
                *(float2*)(C+i0) = make_float2(a0, a1);
                *(float2*)(C+i1) = make_float2(a2, a3);
                *(__half2*)(Ch+i0) = __floats2half2_rn(a0, a1);
                *(__half2*)(Ch+i1) = __floats2half2_rn(a2, a3);
            } else { // EPI==1
                float2 x0 = *(const float2*)(base1+i0), o0 = *(const float2*)(base2+i0);
                float2 x1 = *(const float2*)(base1+i1), o1 = *(const float2*)(base2+i1);
                *(float2*)(C+i0) = make_float2(x0.x+o0.x+alpha*a0, x0.y+o0.y+alpha*a1);
                *(float2*)(C+i1) = make_float2(x1.x+o1.x+alpha*a2, x1.y+o1.y+alpha*a3);
            }
        }
    }
}

// ================= legacy tf32 mma helpers (scan kernels, proven) ============
__device__ __forceinline__ void mma8(float* c, const unsigned* a, const unsigned* b){
    asm volatile("mma.sync.aligned.m16n8k8.row.col.f32.tf32.tf32.f32 "
        "{%0,%1,%2,%3}, {%4,%5,%6,%7}, {%8,%9}, {%0,%1,%2,%3};"
        : "+f"(c[0]), "+f"(c[1]), "+f"(c[2]), "+f"(c[3])
        : "r"(a[0]), "r"(a[1]), "r"(a[2]), "r"(a[3]), "r"(b[0]), "r"(b[1]));
}
#define SMM 36
#define SKM 132
template<int AKM, int BKM>
__device__ __forceinline__ void mma_tile(const unsigned* As, const unsigned* Bs,
                                         float (&acc)[4][4][4], int lane, int wm, int wn){
    int tg = lane & 3, gid = lane >> 2;
    #pragma unroll
    for (int kk = 0; kk < 32; kk += 8){
        unsigned a[4][4], b[4][2];
        #pragma unroll
        for (int mi = 0; mi < 4; mi++){
            int row = wm*64 + mi*16 + gid;
            if (AKM){
                a[mi][0] = As[(kk+tg)*SKM + row];
                a[mi][1] = As[(kk+tg)*SKM + row + 8];
                a[mi][2] = As[(kk+tg+4)*SKM + row];
                a[mi][3] = As[(kk+tg+4)*SKM + row + 8];
            } else {
                a[mi][0] = As[row*SMM + kk+tg];
                a[mi][1] = As[(row+8)*SMM + kk+tg];
                a[mi][2] = As[row*SMM + kk+tg+4];
                a[mi][3] = As[(row+8)*SMM + kk+tg+4];
            }
        }
        #pragma unroll
        for (int ni = 0; ni < 4; ni++){
            int col = wn*32 + ni*8 + gid;
            if (BKM){
                b[ni][0] = Bs[(kk+tg)*SKM + col];
                b[ni][1] = Bs[(kk+tg+4)*SKM + col];
            } else {
                b[ni][0] = Bs[col*SMM + kk+tg];
                b[ni][1] = Bs[col*SMM + kk+tg+4];
            }
        }
        #pragma unroll
        for (int mi = 0; mi < 4; mi++)
            #pragma unroll
            for (int ni = 0; ni < 4; ni++)
                mma8(acc[mi][ni], a[mi], b[ni]);
    }
}
__device__ __forceinline__ void ld_mm(unsigned* S, const float* src, size_t ld, int tid){
    #pragma unroll
    for (int s = 0; s < 4; s++){
        int q = tid + 256*s; int r = q>>3, kc = (q&7)<<2;
        float4 v = *(const float4*)(src + (size_t)r*ld + kc);
        unsigned* d = S + r*SMM + kc;
        d[0]=f2tf(v.x); d[1]=f2tf(v.y); d[2]=f2tf(v.z); d[3]=f2tf(v.w);
    }
}
__device__ __forceinline__ void ld_km(unsigned* S, const float* src, size_t ld, int tid){
    #pragma unroll
    for (int s = 0; s < 4; s++){
        int q = tid + 256*s; int kk = q>>5, nc = (q&31)<<2;
        float4 v = *(const float4*)(src + (size_t)kk*ld + nc);
        unsigned* d = S + kk*SKM + nc;
        d[0]=f2tf(v.x); d[1]=f2tf(v.y); d[2]=f2tf(v.z); d[3]=f2tf(v.w);
    }
}

// ---------------- rmsnorm (half out) ----------------------------------------
__global__ void rmsnorm_k(const float* __restrict__ x, const float* __restrict__ w) {
    int row = blockIdx.x;
    const float* xr = x + (size_t)row*DD;
    __half* o = g_xnh + (size_t)row*DD;
    float s = 0.f;
    for (int d = threadIdx.x; d < DD; d += blockDim.x) { float v = xr[d]; s += v*v; }
    __shared__ float red[32];
    for (int off = 16; off; off >>= 1) s += __shfl_down_sync(0xffffffffu, s, off);
    if ((threadIdx.x & 31) == 0) red[threadIdx.x >> 5] = s;
    __syncthreads();
    if (threadIdx.x < 32) {
        float t = (threadIdx.x < (blockDim.x >> 5)) ? red[threadIdx.x] : 0.f;
        for (int off = 16; off; off >>= 1) t += __shfl_down_sync(0xffffffffu, t, off);
        if (threadIdx.x == 0) red[0] = t;
    }
    __syncthreads();
    float scale = rsqrtf(red[0] / (float)DD + EPS);
    for (int d = threadIdx.x; d < DD; d += blockDim.x)
        o[d] = __float2half_rn(xr[d] * scale * w[d]);
}

// ---------------- fp32 -> fp16 convert (weights, reads) ---------------------
__global__ void f2h_k(const float* __restrict__ src, __half* __restrict__ dst, long n4){
    long i = (long)blockIdx.x*256 + threadIdx.x;
    if (i < n4){
        float4 v = ((const float4*)src)[i];
        ((__half2*)dst)[2*i]   = __floats2half2_rn(v.x, v.y);
        ((__half2*)dst)[2*i+1] = __floats2half2_rn(v.z, v.w);
    }
}

// ---------------- depthwise causal conv + silu gate (half io) ---------------
__global__ void conv_gate_k(const float* __restrict__ cw, const float* __restrict__ cb) {
    long j4 = (long)blockIdx.x*blockDim.x + threadIdx.x;
    const long NV = (long)BT*DI/4;
    if (j4 >= NV) return;
    int e4 = (int)(j4 % (DI/4));
    long bl = j4 / (DI/4);
    int l = (int)(bl % TT);
    int e = e4*4;
    float4 acc = *(const float4*)(cb + e);
    #pragma unroll
    for (int jj = 0; jj < 4; jj++){
        int ll = l - 3 + jj;
        if (ll >= 0){
            const __half2* vp = (const __half2*)(g_valh + (bl-(3-jj))*DI + e);
            float2 v01 = __half22float2(vp[0]);
            float2 v23 = __half22float2(vp[1]);
            acc.x += v01.x * cw[(e+0)*4+jj];
            acc.y += v01.y * cw[(e+1)*4+jj];
            acc.z += v23.x * cw[(e+2)*4+jj];
            acc.w += v23.y * cw[(e+3)*4+jj];
        }
    }
    const __half2* gp = (const __half2*)(g_gateh + j4*4);
    float2 g01 = __half22float2(gp[0]);
    float2 g23 = __half22float2(gp[1]);
    float rx = (acc.x/(1.f+expf(-acc.x))) * (g01.x/(1.f+expf(-g01.x)));
    float ry = (acc.y/(1.f+expf(-acc.y))) * (g01.y/(1.f+expf(-g01.y)));
    float rz = (acc.z/(1.f+expf(-acc.z))) * (g23.x/(1.f+expf(-g23.x)));
    float rw = (acc.w/(1.f+expf(-acc.w))) * (g23.y/(1.f+expf(-g23.y)));
    __half2* up = (__half2*)(g_uh + j4*4);
    up[0] = __floats2half2_rn(rx, ry);
    up[1] = __floats2half2_rn(rz, rw);
}

// ---------------- batched U_m = (v*gw)^T @ k (legacy tf32 mma) --------------
__global__ void __launch_bounds__(256)
u_batch_k(const float* __restrict__ decay_p){
    __shared__ unsigned As[32*SKM], Bs[32*SKM];
    int z = blockIdx.z, b = z/(NCH-1), mch = z%(NCH-1);
    int bm = blockIdx.y*128, bn = blockIdx.x*128;
    int tid=threadIdx.x, lane=tid&31, warp=tid>>5, wm=warp>>2, wn=warp&3;
    float gamma = 1.f/(1.f+expf(-decay_p[0]));
    float lg = logf(gamma);
    float acc[4][4][4];
    #pragma unroll
    for (int i=0;i<4;i++)
        #pragma unroll
        for(int j=0;j<4;j++)
            #pragma unroll
            for(int q=0;q<4;q++) acc[i][j][q]=0.f;
    const float* vb = g_v   + ((size_t)b*TT + (size_t)mch*CH)*DD;
    const float* kb = g_out + ((size_t)b*TT + (size_t)mch*CH)*DD;
    for (int c0 = 0; c0 < CH; c0 += 32){
        #pragma unroll
        for (int s=0;s<4;s++){
            int q = tid+256*s; int kk=q>>5, mc=(q&31)<<2;
            int c = c0+kk;
            float gw = expf((float)(CH-1-c)*lg);
            float4 vv = *(const float4*)(vb + (size_t)c*DD + bm + mc);
            unsigned* d = As + kk*SKM + mc;
            d[0]=f2tf(vv.x*gw); d[1]=f2tf(vv.y*gw); d[2]=f2tf(vv.z*gw); d[3]=f2tf(vv.w*gw);
        }
        #pragma unroll
        for (int s=0;s<4;s++){
            int q = tid+256*s; int kk=q>>5, nc=(q&31)<<2;
            int c = c0+kk;
            float4 kv;
            if (mch==0 && c==0) kv = make_float4(0.f,0.f,0.f,0.f);
            else kv = *(const float4*)(kb + (size_t)(c-1)*DD + bn + nc);
            unsigned* d = Bs + kk*SKM + nc;
            d[0]=f2tf(kv.x); d[1]=f2tf(kv.y); d[2]=f2tf(kv.z); d[3]=f2tf(kv.w);
        }
        __syncthreads();
        mma_tile<1,1>(As, Bs, acc, lane, wm, wn);
        __syncthreads();
    }
    float* Wout = g_Wb + ((size_t)mch*BB + b)*(size_t)DD*DD;
    int tg=lane&3, gid=lane>>2;
    #pragma unroll
    for (int mi=0;mi<4;mi++){
        #pragma unroll
        for (int ni=0;ni<4;ni++){
            int row = bm + wm*64 + mi*16 + gid;
            int col = bn + wn*32 + ni*8 + 2*tg;
            *(float2*)(Wout + (size_t)row*DD + col)     = make_float2(acc[mi][ni][0], acc[mi][ni][1]);
            *(float2*)(Wout + (size_t)(row+8)*DD + col) = make_float2(acc[mi][ni][2], acc[mi][ni][3]);
        }
    }
}

// ---------------- grouped serial scan: 4 AXPY steps per launch --------------
__global__ void wscan4_k(int s0, int cnt, const float* __restrict__ decay_p){
    const size_t n = (size_t)BB*DD*DD;
    size_t i = ((size_t)blockIdx.x*256 + threadIdx.x)*4;
    if (i >= n) return;
    float gamma = 1.f/(1.f+expf(-decay_p[0]));
    float gC = expf(128.f*logf(gamma));
    float4 p = *(const float4*)(g_Wb + (size_t)(s0-1)*n + i);
    for (int j = 0; j < cnt; j++){
        float4* cur = (float4*)(g_Wb + (size_t)(s0+j)*n + i);
        float4 c = *cur;
        c.x += gC*p.x; c.y += gC*p.y; c.z += gC*p.z; c.w += gC*p.w;
        *cur = c; p = c;
    }
}

// ---------------- batched masked S (legacy tf32 mma) ------------------------
__global__ void __launch_bounds__(256)
s_batch_k(const float* __restrict__ decay_p){
    __shared__ unsigned As[128*SMM], Bs[128*SMM];
    int z = blockIdx.x, b = z/NCH, n = z%NCH;
    int tid=threadIdx.x, lane=tid&31, warp=tid>>5, wm=warp>>2, wn=warp&3;
    float acc[4][4][4];
    #pragma unroll
    for (int i=0;i<4;i++)
        #pragma unroll
        for(int j=0;j<4;j++)
            #pragma unroll
            for(int q=0;q<4;q++) acc[i][j][q]=0.f;
    const float* rb = g_out + ((size_t)b*TT + (size_t)n*CH)*DD;
    for (int k0 = 0; k0 < DD; k0 += 32){
        ld_mm(As, rb + k0, DD, tid);
        #pragma unroll
        for (int s=0;s<4;s++){
            int q = tid+256*s; int e=q>>3, kc=(q&7)<<2;
            float4 v;
            if (n==0 && e==0) v = make_float4(0.f,0.f,0.f,0.f);
            else v = *(const float4*)(rb + (size_t)(e-1)*DD + k0 + kc);
            unsigned* d = Bs + e*SMM + kc;
            d[0]=f2tf(v.x); d[1]=f2tf(v.y); d[2]=f2tf(v.z); d[3]=f2tf(v.w);
        }
        __syncthreads();
        mma_tile<0,0>(As, Bs, acc, lane, wm, wn);
        __syncthreads();
    }
    float gamma = 1.f/(1.f+expf(-decay_p[0]));
    float lg = logf(gamma);
    float* smb = g_SM + ((size_t)b*NCH + n)*CH*CH;
    int tg=lane&3, gid=lane>>2;
    #pragma unroll
    for (int mi=0;mi<4;mi++){
        #pragma unroll
        for (int ni=0;ni<4;ni++){
            int c0r = wm*64 + mi*16 + gid;
            int e0c = wn*32 + ni*8 + 2*tg;
            #pragma unroll
            for (int q=0;q<4;q++){
                int c = c0r + ((q>=2)?8:0);
                int e = e0c + (q&1);
                float v = (c>e) ? expf((float)(c-1-e)*lg)*acc[mi][ni][q] : 0.f;
                smb[(size_t)c*CH + e] = v;
            }
        }
    }
}

// ---------------- batched intra: reads = SM @ v (legacy tf32 mma) -----------
__global__ void __launch_bounds__(256)
intra_k(){
    __shared__ unsigned As[128*SMM], Bs[32*SKM];
    int z = blockIdx.z, b = z/NCH, n = z%NCH;
    int bn = blockIdx.x*128;
    int tid=threadIdx.x, lane=tid&31, warp=tid>>5, wm=warp>>2, wn=warp&3;
    float acc[4][4][4];
    #pragma unroll
    for (int i=0;i<4;i++)
        #pragma unroll
        for(int j=0;j<4;j++)
            #pragma unroll
            for(int q=0;q<4;q++) acc[i][j][q]=0.f;
    const float* smb = g_SM + ((size_t)b*NCH+n)*CH*CH;
    const float* vb  = g_v  + ((size_t)b*TT + (size_t)n*CH)*DD;
    for (int e0=0;e0<CH;e0+=32){
        ld_mm(As, smb + e0, CH, tid);
        ld_km(Bs, vb + (size_t)e0*DD + bn, DD, tid);
        __syncthreads();
        mma_tile<0,1>(As, Bs, acc, lane, wm, wn);
        __syncthreads();
    }
    float* ob = g_reads + ((size_t)b*TT + (size_t)n*CH)*DD + bn;
    int tg=lane&3, gid=lane>>2;
    #pragma unroll
    for (int mi=0;mi<4;mi++){
        #pragma unroll
        for (int ni=0;ni<4;ni++){
            int row = wm*64 + mi*16 + gid;
            int col = wn*32 + ni*8 + 2*tg;
            *(float2*)(ob + (size_t)row*DD + col)     = make_float2(acc[mi][ni][0], acc[mi][ni][1]);
            *(float2*)(ob + (size_t)(row+8)*DD + col) = make_float2(acc[mi][ni][2], acc[mi][ni][3]);
        }
    }
}

// ---------------- batched inter: reads += gp[c]*(r @ W_n^T) (legacy) --------
__global__ void __launch_bounds__(256)
inter_k(const float* __restrict__ decay_p){
    __shared__ unsigned As[128*SMM], Bs[128*SMM];
    int z = blockIdx.z, b = z/(NCH-1), n = z%(NCH-1) + 1;
    int bn = blockIdx.x*128;
    int tid=threadIdx.x, lane=tid&31, warp=tid>>5, wm=warp>>2, wn=warp&3;
    float acc[4][4][4];
    #pragma unroll
    for (int i=0;i<4;i++)
        #pragma unroll
        for(int j=0;j<4;j++)
            #pragma unroll
            for(int q=0;q<4;q++) acc[i][j][q]=0.f;
    const float* rb = g_out + ((size_t)b*TT + (size_t)n*CH)*DD;
    const float* Wb = g_Wb + ((size_t)(n-1)*BB + b)*(size_t)DD*DD;
    for (int k0=0;k0<DD;k0+=32){
        ld_mm(As, rb + k0, DD, tid);
        ld_mm(Bs, Wb + (size_t)bn*DD + k0, DD, tid);
        __syncthreads();
        mma_tile<0,0>(As, Bs, acc, lane, wm, wn);
        __syncthreads();
    }
    float gamma = 1.f/(1.f+expf(-decay_p[0]));
    float lg = logf(gamma);
    float* ob = g_reads + ((size_t)b*TT + (size_t)n*CH)*DD + bn;
    int tg=lane&3, gid=lane>>2;
    #pragma unroll
    for (int mi=0;mi<4;mi++){
        int row = wm*64+mi*16+gid;
        float s0 = expf((float)row*lg);
        float s1 = expf((float)(row+8)*lg);
        #pragma unroll
        for (int ni=0;ni<4;ni++){
            int col = wn*32+ni*8+2*tg;
            float2* p0 = (float2*)(ob + (size_t)row*DD + col);
            float2* p1 = (float2*)(ob + (size_t)(row+8)*DD + col);
            float2 a0 = *p0, a1 = *p1;
            a0.x += s0*acc[mi][ni][0]; a0.y += s0*acc[mi][ni][1];
            a1.x += s1*acc[mi][ni][2]; a1.y += s1*acc[mi][ni][3];
            *p0 = a0; *p1 = a1;
        }
    }
}

// ---------------- launch ----------------------------------------------------
extern "C" void kernel_launch(void* const* d_in, const int* in_sizes, int n_in,
                              void* d_out, int out_size) {
    const float* x          = (const float*)d_in[0];
    const float* norm_w     = (const float*)d_in[1];
    const float* proj_w     = (const float*)d_in[2];
    const float* gate_w     = (const float*)d_in[3];
    const float* conv_w     = (const float*)d_in[4];
    const float* conv_b     = (const float*)d_in[5];
    const float* out_proj_w = (const float*)d_in[6];
    const float* write_w    = (const float*)d_in[7];
    const float* read_w     = (const float*)d_in[8];
    const float* decay      = (const float*)d_in[9];
    const float* log_alpha  = (const float*)d_in[10];
    float* out = (float*)d_out;

    __half *xnh, *valh, *gateh, *uh, *oh, *readsh, *wth;
    float *o, *v, *reads, *wb;
    cudaGetSymbolAddress((void**)&xnh,    g_xnh);
    cudaGetSymbolAddress((void**)&valh,   g_valh);
    cudaGetSymbolAddress((void**)&gateh,  g_gateh);
    cudaGetSymbolAddress((void**)&uh,     g_uh);
    cudaGetSymbolAddress((void**)&oh,     g_oh);
    cudaGetSymbolAddress((void**)&readsh, g_readsh);
    cudaGetSymbolAddress((void**)&wth,    g_wth);
    cudaGetSymbolAddress((void**)&o,      g_out);
    cudaGetSymbolAddress((void**)&v,      g_v);
    cudaGetSymbolAddress((void**)&reads,  g_reads);
    cudaGetSymbolAddress((void**)&wb,     g_Wb);

    // 0. weights -> fp16
    f2h_k<<<(294912+255)/256, 256>>>(proj_w,     wth + W_PROJ, 294912);
    f2h_k<<<(294912+255)/256, 256>>>(gate_w,     wth + W_GATE, 294912);
    f2h_k<<<(294912+255)/256, 256>>>(out_proj_w, wth + W_OUTP, 294912);
    f2h_k<<<(147456+255)/256, 256>>>(write_w,    wth + W_WRIT, 147456);
    f2h_k<<<(147456+255)/256, 256>>>(read_w,     wth + W_READ, 147456);
    // 1. rmsnorm (half out)
    rmsnorm_k<<<BT, 256>>>(x, norm_w);
    // 2. proj / gate GEMMs (fp16 TC): [32768,768] x [1536,768]^T
    dim3 g1(DI/128, BT/128);
    gemm_h<5><<<g1, 256>>>(xnh, wth + W_PROJ, nullptr, valh,  DD, DI, nullptr, nullptr, nullptr);
    gemm_h<5><<<g1, 256>>>(xnh, wth + W_GATE, nullptr, gateh, DD, DI, nullptr, nullptr, nullptr);
    // 3. conv + gate (half io)
    conv_gate_k<<<(unsigned)(((long)BT*DI/4 + 255)/256), 256>>>(conv_w, conv_b);
    // 4. out projection (dual store) + write projection
    dim3 g2(DD/128, BT/128);
    gemm_h<6><<<g2, 256>>>(uh, wth + W_OUTP, o, oh, DI, DD, nullptr, nullptr, nullptr);
    gemm_h<0><<<g2, 256>>>(oh, wth + W_WRIT, v, nullptr, DD, DD, nullptr, nullptr, nullptr);
    // 5. chunk outer products (parallel) + grouped serial AXPY scan
    u_batch_k<<<dim3(6,6,BB*(NCH-1)), 256>>>(decay);
    for (int s0 = 1; s0 < NCH-1; s0 += 4){
        int cnt = (NCH-1) - s0; if (cnt > 4) cnt = 4;
        wscan4_k<<<4608, 256>>>(s0, cnt, decay);
    }
    // 6. masked S, intra reads, inter reads
    s_batch_k<<<BB*NCH, 256>>>(decay);
    intra_k<<<dim3(6,1,BB*NCH), 256>>>();
    inter_k<<<dim3(6,1,BB*(NCH-1)), 256>>>(decay);
    // 7. reads -> fp16, final GEMM: out = x + o + alpha*(reads @ read_w^T)
    f2h_k<<<((long)BT*DD/4 + 255)/256, 256>>>(reads, readsh, (long)BT*DD/4);
    gemm_h<1><<<g2, 256>>>(readsh, wth + W_READ, out, nullptr, DD, DD, x, o, log_alpha);
}

// round 7
// speedup vs baseline: 7.6818x; 1.1246x over previous
#include <cuda_runtime.h>
#include <cuda_fp16.h>
#include <math.h>
#include <stdint.h>

#define BB 8
#define TT 4096
#define DD 768
#define DI 1536
#define BT (BB*TT)
#define CH 128
#define NCH 32
#define EPS 1e-5f

// ---------------- scratch (device globals) ----------------------------------
__device__ __half g_xnh[(size_t)BT*DD];
__device__ __half g_valh[(size_t)BT*DI];
__device__ __half g_gateh[(size_t)BT*DI];
__device__ __half g_uh[(size_t)BT*DI];
__device__ __half g_oh[(size_t)BT*DD];
__device__ __half g_readsh[(size_t)BT*DD];
__device__ __half g_wth[4718592];                  // fp16 weights
__device__ __half g_Wbh[(size_t)(NCH-1)*BB*DD*DD]; // fp16 W slots
__device__ float g_out[(size_t)BT*DD];             // conv-mix out (fp32 residual)
__device__ float g_v[(size_t)BT*DD];               // write projection (fp32, scan)
__device__ float g_reads[(size_t)BT*DD];           // attention reads (fp32)
__device__ float g_SM[(size_t)BB*NCH*CH*CH];       // masked S (fp32, for intra)

#define W_PROJ 0
#define W_GATE 1179648
#define W_OUTP 2359296
#define W_WRIT 3538944
#define W_READ 4128768

// ---------------- small helpers ---------------------------------------------
__device__ __forceinline__ unsigned f2tf(float x){
    unsigned u; asm("cvt.rna.tf32.f32 %0, %1;" : "=r"(u) : "f"(x)); return u;
}
__device__ __forceinline__ unsigned smem_u32(const void* p){
    return (unsigned)__cvta_generic_to_shared(p);
}
__device__ __forceinline__ void cpa16(unsigned s, const void* g){
    asm volatile("cp.async.cg.shared.global [%0], [%1], 16;" :: "r"(s), "l"(g));
}

// ================= fp16 legacy-TC GEMM machinery ============================
#define SMH 20

__device__ __forceinline__ void mma16(float* c, const unsigned* a, const unsigned* b){
    asm volatile("mma.sync.aligned.m16n8k16.row.col.f32.f16.f16.f32 "
        "{%0,%1,%2,%3}, {%4,%5,%6,%7}, {%8,%9}, {%0,%1,%2,%3};"
        : "+f"(c[0]), "+f"(c[1]), "+f"(c[2]), "+f"(c[3])
        : "r"(a[0]), "r"(a[1]), "r"(a[2]), "r"(a[3]), "r"(b[0]), "r"(b[1]));
}

__device__ __forceinline__ void ldh(unsigned* S, const __half* src, int ldk, int tid){
    unsigned sb = smem_u32(S);
    #pragma unroll
    for (int s = 0; s < 2; s++){
        int q = tid + 256*s;              // 512 x 16B = 128 rows x 32 halfs
        int r = q>>2, kc8 = (q&3)<<3;
        cpa16(sb + (unsigned)(r*SMH + (kc8>>1))*4u, src + (size_t)r*ldk + kc8);
    }
}

__device__ __forceinline__ void mma_tile_h(const unsigned* As, const unsigned* Bs,
                                           float (&acc)[4][4][4], int lane, int wm, int wn){
    int tg = lane & 3, gid = lane >> 2;
    #pragma unroll
    for (int kk2 = 0; kk2 < 16; kk2 += 8){
        unsigned a[4][4], b[4][2];
        #pragma unroll
        for (int mi = 0; mi < 4; mi++){
            int row = wm*64 + mi*16 + gid;
            a[mi][0] = As[row*SMH + kk2 + tg];
            a[mi][1] = As[(row+8)*SMH + kk2 + tg];
            a[mi][2] = As[row*SMH + kk2 + tg + 4];
            a[mi][3] = As[(row+8)*SMH + kk2 + tg + 4];
        }
        #pragma unroll
        for (int ni = 0; ni < 4; ni++){
            int col = wn*32 + ni*8 + gid;
            b[ni][0] = Bs[col*SMH + kk2 + tg];
            b[ni][1] = Bs[col*SMH + kk2 + tg + 4];
        }
        #pragma unroll
        for (int mi = 0; mi < 4; mi++)
            #pragma unroll
            for (int ni = 0; ni < 4; ni++)
                mma16(acc[mi][ni], a[mi], b[ni]);
    }
}

// EPI: 0 fp32 store; 1 final (base1+base2+alpha*acc); 2 inter (reads += gp*acc,
//      dual store); 5 half store; 6 dual store
template<int EPI>
__global__ void __launch_bounds__(256)
gemm_h(const __half* __restrict__ A, const __half* __restrict__ Bw,
       float* __restrict__ C, __half* __restrict__ Ch, int K, int N,
       const float* __restrict__ base1, const float* __restrict__ base2,
       const float* __restrict__ sp)
{
    __shared__ unsigned As[2][128*SMH], Bs[2][128*SMH];
    int tid = threadIdx.x, lane = tid&31, warp = tid>>5;
    int wm = warp>>2, wn = warp&3;
    int bn = blockIdx.x*128;
    size_t bm, aoff, boff, coff;
    if (EPI == 2){
        int z = blockIdx.z, b = z/(NCH-1), n = z%(NCH-1) + 1;
        aoff = ((size_t)b*TT + (size_t)n*CH)*DD;
        boff = ((size_t)(n-1)*BB + b)*(size_t)DD*DD;
        coff = aoff; bm = 0;
    } else { bm = (size_t)blockIdx.y*128; aoff = 0; boff = 0; coff = 0; }

    float acc[4][4][4];
    #pragma unroll
    for (int i=0;i<4;i++)
        #pragma unroll
        for(int j=0;j<4;j++)
            #pragma unroll
            for(int q=0;q<4;q++) acc[i][j][q]=0.f;

    const __half* Ag = A + aoff + bm*(size_t)K;
    const __half* Bg = Bw + boff + (size_t)bn*K;
    int nk = K >> 5;

    ldh(As[0], Ag, K, tid);
    ldh(Bs[0], Bg, K, tid);
    asm volatile("cp.async.commit_group;" ::: "memory");

    for (int t = 0; t < nk; t++){
        int cur = t & 1;
        if (t + 1 < nk){
            ldh(As[cur^1], Ag + (t+1)*32, K, tid);
            ldh(Bs[cur^1], Bg + (t+1)*32, K, tid);
            asm volatile("cp.async.commit_group;" ::: "memory");
            asm volatile("cp.async.wait_group 1;" ::: "memory");
        } else {
            asm volatile("cp.async.wait_group 0;" ::: "memory");
        }
        __syncthreads();
        mma_tile_h(As[cur], Bs[cur], acc, lane, wm, wn);
        __syncthreads();
    }

    int tg = lane&3, gid = lane>>2;
    float alpha = (EPI==1) ? expf(sp[0]) : 0.f;
    float lg = 0.f;
    if (EPI==2){
        float gamma = 1.f/(1.f+expf(-sp[0]));
        lg = logf(gamma);
    }
    #pragma unroll
    for (int mi=0;mi<4;mi++){
        float s0 = 0.f, s1 = 0.f;
        if (EPI==2){
            s0 = expf((float)(wm*64 + mi*16 + gid)*lg);
            s1 = expf((float)(wm*64 + mi*16 + gid + 8)*lg);
        }
        #pragma unroll
        for (int ni=0;ni<4;ni++){
            int row = (int)bm + wm*64 + mi*16 + gid;
            int col = bn + wn*32 + ni*8 + 2*tg;
            size_t i0 = coff + (size_t)row*N + col;
            size_t i1 = coff + (size_t)(row+8)*N + col;
            float a0 = acc[mi][ni][0], a1 = acc[mi][ni][1];
            float a2 = acc[mi][ni][2], a3 = acc[mi][ni][3];
            if (EPI == 0){
                *(float2*)(C+i0) = make_float2(a0, a1);
                *(float2*)(C+i1) = make_float2(a2, a3);
            } else if (EPI == 5){
                *(__half2*)(Ch+i0) = __floats2half2_rn(a0, a1);
                *(__half2*)(Ch+i1) = __floats2half2_rn(a2, a3);
            } else if (EPI == 6){
                *(float2*)(C+i0) = make_float2(a0, a1);
                *(float2*)(C+i1) = make_float2(a2, a3);
                *(__half2*)(Ch+i0) = __floats2half2_rn(a0, a1);
                *(__half2*)(Ch+i1) = __floats2half2_rn(a2, a3);
            } else if (EPI == 2){
                float2 c0 = *(const float2*)(C+i0);
                float2 c1 = *(const float2*)(C+i1);
                c0.x += s0*a0; c0.y += s0*a1;
                c1.x += s1*a2; c1.y += s1*a3;
                *(float2*)(C+i0) = c0;
                *(float2*)(C+i1) = c1;
                *(__half2*)(Ch+i0) = __floats2half2_rn(c0.x, c0.y);
                *(__half2*)(Ch+i1) = __floats2half2_rn(c1.x, c1.y);
            } else { // EPI==1
                float2 x0 = *(const float2*)(base1+i0), o0 = *(const float2*)(base2+i0);
                float2 x1 = *(const float2*)(base1+i1), o1 = *(const float2*)(base2+i1);
                *(float2*)(C+i0) = make_float2(x0.x+o0.x+alpha*a0, x0.y+o0.y+alpha*a1);
                *(float2*)(C+i1) = make_float2(x1.x+o1.x+alpha*a2, x1.y+o1.y+alpha*a3);
            }
        }
    }
}

// ---------------- batched masked S (fp16 mma) -------------------------------
__global__ void __launch_bounds__(256)
s_batch_h(const float* __restrict__ decay_p){
    __shared__ unsigned As[2][128*SMH], Bs[2][128*SMH];
    int z = blockIdx.x, b = z/NCH, n = z%NCH;
    int tid = threadIdx.x, lane = tid&31, warp = tid>>5;
    int wm = warp>>2, wn = warp&3;
    float acc[4][4][4];
    #pragma unroll
    for (int i=0;i<4;i++)
        #pragma unroll
        for(int j=0;j<4;j++)
            #pragma unroll
            for(int q=0;q<4;q++) acc[i][j][q]=0.f;

    const __half* rb = g_oh + ((size_t)b*TT + (size_t)n*CH)*DD;
    const __half* kb = rb - DD;          // key row e = out[t-1]; row0 invalid iff n==0
    bool z0 = (n == 0);

    // B loader with zero-row handling
    auto ldb = [&](unsigned* S, int k0){
        unsigned sb = smem_u32(S);
        #pragma unroll
        for (int s = 0; s < 2; s++){
            int q = tid + 256*s; int r = q>>2, kc8 = (q&3)<<3;
            if (z0 && r == 0){
                *(uint4*)(S + r*SMH + (kc8>>1)) = make_uint4(0,0,0,0);
            } else {
                cpa16(sb + (unsigned)(r*SMH + (kc8>>1))*4u, kb + (size_t)r*DD + k0 + kc8);
            }
        }
    };

    ldh(As[0], rb, DD, tid);
    ldb(Bs[0], 0);
    asm volatile("cp.async.commit_group;" ::: "memory");
    int nk = DD >> 5;
    for (int t = 0; t < nk; t++){
        int cur = t & 1;
        if (t + 1 < nk){
            ldh(As[cur^1], rb + (t+1)*32, DD, tid);
            ldb(Bs[cur^1], (t+1)*32);
            asm volatile("cp.async.commit_group;" ::: "memory");
            asm volatile("cp.async.wait_group 1;" ::: "memory");
        } else {
            asm volatile("cp.async.wait_group 0;" ::: "memory");
        }
        __syncthreads();
        mma_tile_h(As[cur], Bs[cur], acc, lane, wm, wn);
        __syncthreads();
    }

    float gamma = 1.f/(1.f+expf(-decay_p[0]));
    float lg = logf(gamma);
    float* smb = g_SM + ((size_t)b*NCH + n)*CH*CH;
    int tg=lane&3, gid=lane>>2;
    #pragma unroll
    for (int mi=0;mi<4;mi++){
        #pragma unroll
        for (int ni=0;ni<4;ni++){
            int c0r = wm*64 + mi*16 + gid;
            int e0c = wn*32 + ni*8 + 2*tg;
            #pragma unroll
            for (int q=0;q<4;q++){
                int c = c0r + ((q>=2)?8:0);
                int e = e0c + (q&1);
                float v = (c>e) ? expf((float)(c-1-e)*lg)*acc[mi][ni][q] : 0.f;
                smb[(size_t)c*CH + e] = v;
            }
        }
    }
}

// ================= legacy tf32 mma helpers (u_batch, intra) =================
__device__ __forceinline__ void mma8(float* c, const unsigned* a, const unsigned* b){
    asm volatile("mma.sync.aligned.m16n8k8.row.col.f32.tf32.tf32.f32 "
        "{%0,%1,%2,%3}, {%4,%5,%6,%7}, {%8,%9}, {%0,%1,%2,%3};"
        : "+f"(c[0]), "+f"(c[1]), "+f"(c[2]), "+f"(c[3])
        : "r"(a[0]), "r"(a[1]), "r"(a[2]), "r"(a[3]), "r"(b[0]), "r"(b[1]));
}
#define SMM 36
#define SKM 132
template<int AKM, int BKM>
__device__ __forceinline__ void mma_tile(const unsigned* As, const unsigned* Bs,
                                         float (&acc)[4][4][4], int lane, int wm, int wn){
    int tg = lane & 3, gid = lane >> 2;
    #pragma unroll
    for (int kk = 0; kk < 32; kk += 8){
        unsigned a[4][4], b[4][2];
        #pragma unroll
        for (int mi = 0; mi < 4; mi++){
            int row = wm*64 + mi*16 + gid;
            if (AKM){
                a[mi][0] = As[(kk+tg)*SKM + row];
                a[mi][1] = As[(kk+tg)*SKM + row + 8];
                a[mi][2] = As[(kk+tg+4)*SKM + row];
                a[mi][3] = As[(kk+tg+4)*SKM + row + 8];
            } else {
                a[mi][0] = As[row*SMM + kk+tg];
                a[mi][1] = As[(row+8)*SMM + kk+tg];
                a[mi][2] = As[row*SMM + kk+tg+4];
                a[mi][3] = As[(row+8)*SMM + kk+tg+4];
            }
        }
        #pragma unroll
        for (int ni = 0; ni < 4; ni++){
            int col = wn*32 + ni*8 + gid;
            if (BKM){
                b[ni][0] = Bs[(kk+tg)*SKM + col];
                b[ni][1] = Bs[(kk+tg+4)*SKM + col];
            } else {
                b[ni][0] = Bs[col*SMM + kk+tg];
                b[ni][1] = Bs[col*SMM + kk+tg+4];
            }
        }
        #pragma unroll
        for (int mi = 0; mi < 4; mi++)
            #pragma unroll
            for (int ni = 0; ni < 4; ni++)
                mma8(acc[mi][ni], a[mi], b[ni]);
    }
}
__device__ __forceinline__ void ld_mm(unsigned* S, const float* src, size_t ld, int tid){
    #pragma unroll
    for (int s = 0; s < 4; s++){
        int q = tid + 256*s; int r = q>>3, kc = (q&7)<<2;
        float4 v = *(const float4*)(src + (size_t)r*ld + kc);
        unsigned* d = S + r*SMM + kc;
        d[0]=f2tf(v.x); d[1]=f2tf(v.y); d[2]=f2tf(v.z); d[3]=f2tf(v.w);
    }
}
__device__ __forceinline__ void ld_km(unsigned* S, const float* src, size_t ld, int tid){
    #pragma unroll
    for (int s = 0; s < 4; s++){
        int q = tid + 256*s; int kk = q>>5, nc = (q&31)<<2;
        float4 v = *(const float4*)(src + (size_t)kk*ld + nc);
        unsigned* d = S + kk*SKM + nc;
        d[0]=f2tf(v.x); d[1]=f2tf(v.y); d[2]=f2tf(v.z); d[3]=f2tf(v.w);
    }
}

// ---------------- rmsnorm (half out) ----------------------------------------
__global__ void rmsnorm_k(const float* __restrict__ x, const float* __restrict__ w) {
    int row = blockIdx.x;
    const float* xr = x + (size_t)row*DD;
    __half* o = g_xnh + (size_t)row*DD;
    float s = 0.f;
    for (int d = threadIdx.x; d < DD; d += blockDim.x) { float v = xr[d]; s += v*v; }
    __shared__ float red[32];
    for (int off = 16; off; off >>= 1) s += __shfl_down_sync(0xffffffffu, s, off);
    if ((threadIdx.x & 31) == 0) red[threadIdx.x >> 5] = s;
    __syncthreads();
    if (threadIdx.x < 32) {
        float t = (threadIdx.x < (blockDim.x >> 5)) ? red[threadIdx.x] : 0.f;
        for (int off = 16; off; off >>= 1) t += __shfl_down_sync(0xffffffffu, t, off);
        if (threadIdx.x == 0) red[0] = t;
    }
    __syncthreads();
    float scale = rsqrtf(red[0] / (float)DD + EPS);
    for (int d = threadIdx.x; d < DD; d += blockDim.x)
        o[d] = __float2half_rn(xr[d] * scale * w[d]);
}

// ---------------- fp32 -> fp16 convert (weights) ----------------------------
__global__ void f2h_k(const float* __restrict__ src, __half* __restrict__ dst, long n4){
    long i = (long)blockIdx.x*256 + threadIdx.x;
    if (i < n4){
        float4 v = ((const float4*)src)[i];
        ((__half2*)dst)[2*i]   = __floats2half2_rn(v.x, v.y);
        ((__half2*)dst)[2*i+1] = __floats2half2_rn(v.z, v.w);
    }
}

// ---------------- depthwise causal conv + silu gate (half io) ---------------
__global__ void conv_gate_k(const float* __restrict__ cw, const float* __restrict__ cb) {
    long j4 = (long)blockIdx.x*blockDim.x + threadIdx.x;
    const long NV = (long)BT*DI/4;
    if (j4 >= NV) return;
    int e4 = (int)(j4 % (DI/4));
    long bl = j4 / (DI/4);
    int l = (int)(bl % TT);
    int e = e4*4;
    float4 acc = *(const float4*)(cb + e);
    #pragma unroll
    for (int jj = 0; jj < 4; jj++){
        int ll = l - 3 + jj;
        if (ll >= 0){
            const __half2* vp = (const __half2*)(g_valh + (bl-(3-jj))*DI + e);
            float2 v01 = __half22float2(vp[0]);
            float2 v23 = __half22float2(vp[1]);
            acc.x += v01.x * cw[(e+0)*4+jj];
            acc.y += v01.y * cw[(e+1)*4+jj];
            acc.z += v23.x * cw[(e+2)*4+jj];
            acc.w += v23.y * cw[(e+3)*4+jj];
        }
    }
    const __half2* gp = (const __half2*)(g_gateh + j4*4);
    float2 g01 = __half22float2(gp[0]);
    float2 g23 = __half22float2(gp[1]);
    float rx = (acc.x/(1.f+expf(-acc.x))) * (g01.x/(1.f+expf(-g01.x)));
    float ry = (acc.y/(1.f+expf(-acc.y))) * (g01.y/(1.f+expf(-g01.y)));
    float rz = (acc.z/(1.f+expf(-acc.z))) * (g23.x/(1.f+expf(-g23.x)));
    float rw = (acc.w/(1.f+expf(-acc.w))) * (g23.y/(1.f+expf(-g23.y)));
    __half2* up = (__half2*)(g_uh + j4*4);
    up[0] = __floats2half2_rn(rx, ry);
    up[1] = __floats2half2_rn(rz, rw);
}

// ---------------- batched U_m = (v*gw)^T @ k (tf32, half out) ---------------
__global__ void __launch_bounds__(256)
u_batch_k(const float* __restrict__ decay_p){
    __shared__ unsigned As[32*SKM], Bs[32*SKM];
    int z = blockIdx.z, b = z/(NCH-1), mch = z%(NCH-1);
    int bm = blockIdx.y*128, bn = blockIdx.x*128;
    int tid=threadIdx.x, lane=tid&31, warp=tid>>5, wm=warp>>2, wn=warp&3;
    float gamma = 1.f/(1.f+expf(-decay_p[0]));
    float lg = logf(gamma);
    float acc[4][4][4];
    #pragma unroll
    for (int i=0;i<4;i++)
        #pragma unroll
        for(int j=0;j<4;j++)
            #pragma unroll
            for(int q=0;q<4;q++) acc[i][j][q]=0.f;
    const float* vb = g_v   + ((size_t)b*TT + (size_t)mch*CH)*DD;
    const float* kb = g_out + ((size_t)b*TT + (size_t)mch*CH)*DD;
    for (int c0 = 0; c0 < CH; c0 += 32){
        #pragma unroll
        for (int s=0;s<4;s++){
            int q = tid+256*s; int kk=q>>5, mc=(q&31)<<2;
            int c = c0+kk;
            float gw = expf((float)(CH-1-c)*lg);
            float4 vv = *(const float4*)(vb + (size_t)c*DD + bm + mc);
            unsigned* d = As + kk*SKM + mc;
            d[0]=f2tf(vv.x*gw); d[1]=f2tf(vv.y*gw); d[2]=f2tf(vv.z*gw); d[3]=f2tf(vv.w*gw);
        }
        #pragma unroll
        for (int s=0;s<4;s++){
            int q = tid+256*s; int kk=q>>5, nc=(q&31)<<2;
            int c = c0+kk;
            float4 kv;
            if (mch==0 && c==0) kv = make_float4(0.f,0.f,0.f,0.f);
            else kv = *(const float4*)(kb + (size_t)(c-1)*DD + bn + nc);
            unsigned* d = Bs + kk*SKM + nc;
            d[0]=f2tf(kv.x); d[1]=f2tf(kv.y); d[2]=f2tf(kv.z); d[3]=f2tf(kv.w);
        }
        __syncthreads();
        mma_tile<1,1>(As, Bs, acc, lane, wm, wn);
        __syncthreads();
    }
    __half* Wout = g_Wbh + ((size_t)mch*BB + b)*(size_t)DD*DD;
    int tg=lane&3, gid=lane>>2;
    #pragma unroll
    for (int mi=0;mi<4;mi++){
        #pragma unroll
        for (int ni=0;ni<4;ni++){
            int row = bm + wm*64 + mi*16 + gid;
            int col = bn + wn*32 + ni*8 + 2*tg;
            *(__half2*)(Wout + (size_t)row*DD + col)     = __floats2half2_rn(acc[mi][ni][0], acc[mi][ni][1]);
            *(__half2*)(Wout + (size_t)(row+8)*DD + col) = __floats2half2_rn(acc[mi][ni][2], acc[mi][ni][3]);
        }
    }
}

// ---------------- grouped serial scan on fp16 slots -------------------------
__global__ void wscan4_h(int s0, int cnt, const float* __restrict__ decay_p){
    const size_t n = (size_t)BB*DD*DD;
    size_t i = ((size_t)blockIdx.x*256 + threadIdx.x)*8;
    if (i >= n) return;
    float gamma = 1.f/(1.f+expf(-decay_p[0]));
    float gC = expf(128.f*logf(gamma));
    uint4 pv = *(const uint4*)(g_Wbh + (size_t)(s0-1)*n + i);
    float2 p[4];
    p[0] = __half22float2(*(__half2*)&pv.x);
    p[1] = __half22float2(*(__half2*)&pv.y);
    p[2] = __half22float2(*(__half2*)&pv.z);
    p[3] = __half22float2(*(__half2*)&pv.w);
    for (int j = 0; j < cnt; j++){
        uint4* cur = (uint4*)(g_Wbh + (size_t)(s0+j)*n + i);
        uint4 cv = *cur;
        float2 c[4];
        c[0] = __half22float2(*(__half2*)&cv.x);
        c[1] = __half22float2(*(__half2*)&cv.y);
        c[2] = __half22float2(*(__half2*)&cv.z);
        c[3] = __half22float2(*(__half2*)&cv.w);
        #pragma unroll
        for (int q = 0; q < 4; q++){ c[q].x += gC*p[q].x; c[q].y += gC*p[q].y; p[q] = c[q]; }
        *(__half2*)&cv.x = __floats2half2_rn(c[0].x, c[0].y);
        *(__half2*)&cv.y = __floats2half2_rn(c[1].x, c[1].y);
        *(__half2*)&cv.z = __floats2half2_rn(c[2].x, c[2].y);
        *(__half2*)&cv.w = __floats2half2_rn(c[3].x, c[3].y);
        *cur = cv;
    }
}

// ---------------- batched intra: reads = SM @ v (tf32, dual store) ----------
__global__ void __launch_bounds__(256)
intra_k(){
    __shared__ unsigned As[128*SMM], Bs[32*SKM];
    int z = blockIdx.z, b = z/NCH, n = z%NCH;
    int bn = blockIdx.x*128;
    int tid=threadIdx.x, lane=tid&31, warp=tid>>5, wm=warp>>2, wn=warp&3;
    float acc[4][4][4];
    #pragma unroll
    for (int i=0;i<4;i++)
        #pragma unroll
        for(int j=0;j<4;j++)
            #pragma unroll
            for(int q=0;q<4;q++) acc[i][j][q]=0.f;
    const float* smb = g_SM + ((size_t)b*NCH+n)*CH*CH;
    const float* vb  = g_v  + ((size_t)b*TT + (size_t)n*CH)*DD;
    for (int e0=0;e0<CH;e0+=32){
        ld_mm(As, smb + e0, CH, tid);
        ld_km(Bs, vb + (size_t)e0*DD + bn, DD, tid);
        __syncthreads();
        mma_tile<0,1>(As, Bs, acc, lane, wm, wn);
        __syncthreads();
    }
    size_t ob = ((size_t)b*TT + (size_t)n*CH)*DD + bn;
    int tg=lane&3, gid=lane>>2;
    #pragma unroll
    for (int mi=0;mi<4;mi++){
        #pragma unroll
        for (int ni=0;ni<4;ni++){
            int row = wm*64 + mi*16 + gid;
            int col = wn*32 + ni*8 + 2*tg;
            size_t i0 = ob + (size_t)row*DD + col;
            size_t i1 = ob + (size_t)(row+8)*DD + col;
            *(float2*)(g_reads+i0) = make_float2(acc[mi][ni][0], acc[mi][ni][1]);
            *(float2*)(g_reads+i1) = make_float2(acc[mi][ni][2], acc[mi][ni][3]);
            *(__half2*)(g_readsh+i0) = __floats2half2_rn(acc[mi][ni][0], acc[mi][ni][1]);
            *(__half2*)(g_readsh+i1) = __floats2half2_rn(acc[mi][ni][2], acc[mi][ni][3]);
        }
    }
}

// ---------------- launch ----------------------------------------------------
extern "C" void kernel_launch(void* const* d_in, const int* in_sizes, int n_in,
                              void* d_out, int out_size) {
    const float* x          = (const float*)d_in[0];
    const float* norm_w     = (const float*)d_in[1];
    const float* proj_w     = (const float*)d_in[2];
    const float* gate_w     = (const float*)d_in[3];
    const float* conv_w     = (const float*)d_in[4];
    const float* conv_b     = (const float*)d_in[5];
    const float* out_proj_w = (const float*)d_in[6];
    const float* write_w    = (const float*)d_in[7];
    const float* read_w     = (const float*)d_in[8];
    const float* decay      = (const float*)d_in[9];
    const float* log_alpha  = (const float*)d_in[10];
    float* out = (float*)d_out;

    __half *xnh, *valh, *gateh, *uh, *oh, *readsh, *wth, *wbh;
    float *o, *v, *reads;
    cudaGetSymbolAddress((void**)&xnh,    g_xnh);
    cudaGetSymbolAddress((void**)&valh,   g_valh);
    cudaGetSymbolAddress((void**)&gateh,  g_gateh);
    cudaGetSymbolAddress((void**)&uh,     g_uh);
    cudaGetSymbolAddress((void**)&oh,     g_oh);
    cudaGetSymbolAddress((void**)&readsh, g_readsh);
    cudaGetSymbolAddress((void**)&wth,    g_wth);
    cudaGetSymbolAddress((void**)&wbh,    g_Wbh);
    cudaGetSymbolAddress((void**)&o,      g_out);
    cudaGetSymbolAddress((void**)&v,      g_v);
    cudaGetSymbolAddress((void**)&reads,  g_reads);

    // 0. weights -> fp16
    f2h_k<<<(294912+255)/256, 256>>>(proj_w,     wth + W_PROJ, 294912);
    f2h_k<<<(294912+255)/256, 256>>>(gate_w,     wth + W_GATE, 294912);
    f2h_k<<<(294912+255)/256, 256>>>(out_proj_w, wth + W_OUTP, 294912);
    f2h_k<<<(147456+255)/256, 256>>>(write_w,    wth + W_WRIT, 147456);
    f2h_k<<<(147456+255)/256, 256>>>(read_w,     wth + W_READ, 147456);
    // 1. rmsnorm (half out)
    rmsnorm_k<<<BT, 256>>>(x, norm_w);
    // 2. proj / gate GEMMs (fp16 TC)
    dim3 g1(DI/128, BT/128);
    gemm_h<5><<<g1, 256>>>(xnh, wth + W_PROJ, nullptr, valh,  DD, DI, nullptr, nullptr, nullptr);
    gemm_h<5><<<g1, 256>>>(xnh, wth + W_GATE, nullptr, gateh, DD, DI, nullptr, nullptr, nullptr);
    // 3. conv + gate (half io)
    conv_gate_k<<<(unsigned)(((long)BT*DI/4 + 255)/256), 256>>>(conv_w, conv_b);
    // 4. out projection (dual store) + write projection (fp32 for scan)
    dim3 g2(DD/128, BT/128);
    gemm_h<6><<<g2, 256>>>(uh, wth + W_OUTP, o, oh, DI, DD, nullptr, nullptr, nullptr);
    gemm_h<0><<<g2, 256>>>(oh, wth + W_WRIT, v, nullptr, DD, DD, nullptr, nullptr, nullptr);
    // 5. chunk outer products (tf32, fp16 out) + grouped fp16 AXPY scan
    u_batch_k<<<dim3(6,6,BB*(NCH-1)), 256>>>(decay);
    for (int s0 = 1; s0 < NCH-1; s0 += 4){
        int cnt = (NCH-1) - s0; if (cnt > 4) cnt = 4;
        wscan4_h<<<2304, 256>>>(s0, cnt, decay);
    }
    // 6. masked S (fp16), intra (tf32, dual store), inter (fp16, accumulate)
    s_batch_h<<<BB*NCH, 256>>>(decay);
    intra_k<<<dim3(6,1,BB*NCH), 256>>>();
    gemm_h<2><<<dim3(6,1,BB*(NCH-1)), 256>>>(oh, wbh, reads, readsh, DD, DD, nullptr, nullptr, decay);
    // 7. final: out = x + o + alpha*(reads @ read_w^T)
    gemm_h<1><<<g2, 256>>>(readsh, wth + W_READ, out, nullptr, DD, DD, x, o, log_alpha);
}